// round 5
// baseline (speedup 1.0000x reference)
#include <cuda_runtime.h>
#include <math.h>
#include <stdint.h>

#define TOKENS 4096
#define DMODEL 1024
#define DINNER 2048
#define DSTATE 16
#define SEQL   2048

// Scratch (static device globals — no runtime allocation allowed)
__device__ __align__(256) float g_xz  [TOKENS * 2 * DINNER];  // GEMM1 out: xi-preconv | z
__device__ __align__(256) float g_xi  [TOKENS * DINNER];      // conv+silu output
__device__ __align__(256) float g_y   [TOKENS * DINNER];      // scan output (tf32-rounded)
__device__ __align__(256) float g_dbc [TOKENS * 33];
__device__ __align__(256) float g_dbcp[8][TOKENS * 33];
__device__ __align__(256) float g_xr  [TOKENS * DMODEL];      // rna-rounded x
__device__ __align__(256) float g_wr  [2 * DINNER * DMODEL];  // rna-rounded W_in
__device__ __align__(256) float g_wor [DMODEL * DINNER];      // rna-rounded W_out

// ---------------------------------------------------------------------------
__device__ __forceinline__ uint32_t f2tf32(float x) {
    uint32_t r;
    asm("cvt.rna.tf32.f32 %0, %1;" : "=r"(r) : "f"(x));
    return r;
}

__device__ __forceinline__ void mma_tf32(float* c, const uint32_t* a, const uint32_t* b) {
    asm volatile(
        "mma.sync.aligned.m16n8k8.row.col.f32.tf32.tf32.f32 "
        "{%0,%1,%2,%3}, {%4,%5,%6,%7}, {%8,%9}, {%0,%1,%2,%3};"
        : "+f"(c[0]), "+f"(c[1]), "+f"(c[2]), "+f"(c[3])
        : "r"(a[0]), "r"(a[1]), "r"(a[2]), "r"(a[3]), "r"(b[0]), "r"(b[1]));
}

__device__ __forceinline__ void cp_async16(void* smem_dst, const void* gmem_src) {
    uint32_t s = (uint32_t)__cvta_generic_to_shared(smem_dst);
    asm volatile("cp.async.cg.shared.global [%0], [%1], 16;" :: "r"(s), "l"(gmem_src));
}

// ---------------------------------------------------------------------------
// TF32 mma.sync GEMM:  C[M,N] = A[M,K] * B[N,K]^T  (row-major A, B)
// Block 128x256, BK=32, 8 warps (2x4) with 64x64 warp tiles, 3-stage cp.async.
// Operands MUST be pre-rounded to tf32 (rna) in gmem — no in-kernel cvt.
// ---------------------------------------------------------------------------
#define BM 128
#define BN 256
#define BK 32
#define SSTRIDE 36                        // floats per smem row (16B aligned)
#define A_FLOATS (BM * SSTRIDE)           // 4608
#define B_FLOATS (BN * SSTRIDE)           // 9216
#define STAGE_FLOATS (A_FLOATS + B_FLOATS)// 13824
#define GEMM_SMEM (3 * STAGE_FLOATS * 4)  // 165888 bytes

__global__ void __launch_bounds__(256, 1)
tf32_gemm_nt(const float* __restrict__ A, const float* __restrict__ B,
             float* __restrict__ C, int M, int N, int K) {
    extern __shared__ float sm[];

    const int tid  = threadIdx.x;
    const int wid  = tid >> 5;
    const int lane = tid & 31;
    const int gid  = lane >> 2;           // 0..7
    const int t4   = lane & 3;            // 0..3
    const int wm   = wid & 1;             // 2 warps along M (64 rows each)
    const int wn   = wid >> 1;            // 4 warps along N (64 cols each)
    const int row0 = blockIdx.y * BM;
    const int col0 = blockIdx.x * BN;

    // loader mapping: 8 threads per row, 4 floats each
    const int lr = tid >> 3;              // 0..31 base row (stride 32)
    const int lc = (tid & 7) * 4;         // 0,4,...,28

    float acc[4][8][4] = {};

    const int niter = K / BK;

    auto load_stage = [&](int stage, int k0) {
        float* Sa = sm + stage * STAGE_FLOATS;
        float* Sb = Sa + A_FLOATS;
#pragma unroll
        for (int i = 0; i < 4; i++) {     // A: 128 rows
            int m = lr + i * 32;
            cp_async16(&Sa[m * SSTRIDE + lc], A + (size_t)(row0 + m) * K + k0 + lc);
        }
#pragma unroll
        for (int i = 0; i < 8; i++) {     // B: 256 rows
            int n = lr + i * 32;
            cp_async16(&Sb[n * SSTRIDE + lc], B + (size_t)(col0 + n) * K + k0 + lc);
        }
    };

    load_stage(0, 0);
    asm volatile("cp.async.commit_group;");
    if (niter > 1) load_stage(1, BK);
    asm volatile("cp.async.commit_group;");

    int s = 0;
    for (int it = 0; it < niter; it++) {
        asm volatile("cp.async.wait_group 1;");
        __syncthreads();

        if (it + 2 < niter) load_stage((it + 2) % 3, (it + 2) * BK);
        asm volatile("cp.async.commit_group;");

        const float* Ab = sm + s * STAGE_FLOATS;
        const float* Bb = Ab + A_FLOATS;
#pragma unroll
        for (int kk = 0; kk < 4; kk++) {
            const int cc = kk * 8 + t4;
            uint32_t af[4][4], bf[8][2];
#pragma unroll
            for (int fm = 0; fm < 4; fm++) {
                int r = wm * 64 + fm * 16 + gid;
                af[fm][0] = __float_as_uint(Ab[r * SSTRIDE + cc]);
                af[fm][1] = __float_as_uint(Ab[(r + 8) * SSTRIDE + cc]);
                af[fm][2] = __float_as_uint(Ab[r * SSTRIDE + cc + 4]);
                af[fm][3] = __float_as_uint(Ab[(r + 8) * SSTRIDE + cc + 4]);
            }
#pragma unroll
            for (int fn = 0; fn < 8; fn++) {
                int nn = wn * 64 + fn * 8 + gid;
                bf[fn][0] = __float_as_uint(Bb[nn * SSTRIDE + cc]);
                bf[fn][1] = __float_as_uint(Bb[nn * SSTRIDE + cc + 4]);
            }
#pragma unroll
            for (int fm = 0; fm < 4; fm++)
#pragma unroll
                for (int fn = 0; fn < 8; fn++)
                    mma_tf32(acc[fm][fn], af[fm], bf[fn]);
        }
        __syncthreads();
        s = (s + 1) % 3;
    }

#pragma unroll
    for (int fm = 0; fm < 4; fm++) {
        int r = row0 + wm * 64 + fm * 16 + gid;
#pragma unroll
        for (int fn = 0; fn < 8; fn++) {
            int cbase = col0 + wn * 64 + fn * 8 + t4 * 2;
            float2* p0 = (float2*)&C[(size_t)r * N + cbase];
            float2* p1 = (float2*)&C[(size_t)(r + 8) * N + cbase];
            *p0 = make_float2(acc[fm][fn][0], acc[fm][fn][1]);
            *p1 = make_float2(acc[fm][fn][2], acc[fm][fn][3]);
        }
    }
}

// ---------------------------------------------------------------------------
// rna-round fp32 -> tf32-exact fp32 (GEMM operand prep)
// ---------------------------------------------------------------------------
__global__ void round_k(const float* __restrict__ in, float* __restrict__ out, int n4) {
    int i = blockIdx.x * blockDim.x + threadIdx.x;
    if (i >= n4) return;
    float4 v = ((const float4*)in)[i];
    v.x = __uint_as_float(f2tf32(v.x));
    v.y = __uint_as_float(f2tf32(v.y));
    v.z = __uint_as_float(f2tf32(v.z));
    v.w = __uint_as_float(f2tf32(v.w));
    ((float4*)out)[i] = v;
}

// ---------------------------------------------------------------------------
// Causal depthwise conv (width 4) + bias + SiLU on first half of xz -> g_xi
// ---------------------------------------------------------------------------
__global__ void conv_silu_k(const float* __restrict__ cw, const float* __restrict__ cb) {
    int idx = blockIdx.x * blockDim.x + threadIdx.x;
    int d = idx & (DINNER - 1);
    int t = idx >> 11;
    int l = t & (SEQL - 1);
    float w0 = cw[d * 4 + 0], w1 = cw[d * 4 + 1], w2 = cw[d * 4 + 2], w3 = cw[d * 4 + 3];
    float acc = cb[d];
    size_t base = (size_t)t * (2 * DINNER) + d;
    if (l >= 3) acc += g_xz[base - 3 * (size_t)(2 * DINNER)] * w0;
    if (l >= 2) acc += g_xz[base - 2 * (size_t)(2 * DINNER)] * w1;
    if (l >= 1) acc += g_xz[base - 1 * (size_t)(2 * DINNER)] * w2;
    acc += g_xz[base] * w3;
    g_xi[idx] = acc / (1.f + __expf(-acc));
}

// ---------------------------------------------------------------------------
// x_dbl split-K partials + deterministic reduce (fp32)
// ---------------------------------------------------------------------------
__global__ void xdbl_part_k(const float* __restrict__ Wx) {
    __shared__ float Xs[64][33];
    __shared__ float Ws[33][33];
    const int tx = threadIdx.x, ty = threadIdx.y;   // (33,8)
    const int tid = ty * 33 + tx;
    const int tok0 = blockIdx.x * 64;
    const int kbase = blockIdx.y * 256;
    float acc[8] = {};
    for (int k0 = kbase; k0 < kbase + 256; k0 += 32) {
        for (int i = tid; i < 64 * 32; i += 264) {
            int tt = i >> 5, kk = i & 31;
            Xs[tt][kk] = g_xi[(size_t)(tok0 + tt) * DINNER + k0 + kk];
        }
        for (int i = tid; i < 33 * 32; i += 264) {
            int e = i >> 5, kk = i & 31;
            Ws[e][kk] = Wx[(size_t)e * DINNER + k0 + kk];
        }
        __syncthreads();
#pragma unroll
        for (int kk = 0; kk < 32; kk++) {
            float w = Ws[tx][kk];
#pragma unroll
            for (int i = 0; i < 8; i++)
                acc[i] += Xs[ty * 8 + i][kk] * w;
        }
        __syncthreads();
    }
#pragma unroll
    for (int i = 0; i < 8; i++)
        g_dbcp[blockIdx.y][(size_t)(tok0 + ty * 8 + i) * 33 + tx] = acc[i];
}

__global__ void xdbl_reduce_k() {
    int i = blockIdx.x * blockDim.x + threadIdx.x;
    if (i >= TOKENS * 33) return;
    float s = 0.f;
#pragma unroll
    for (int p = 0; p < 8; p++) s += g_dbcp[p][i];
    g_dbc[i] = s;
}

// ---------------------------------------------------------------------------
// Selective scan (softplus fused; +D*xi; *silu(z); tf32-rounds y for GEMM2)
// ---------------------------------------------------------------------------
#define CH 32
#define PSTRIDE 17

__global__ void __launch_bounds__(256)
scan_k(const float* __restrict__ A_log, const float* __restrict__ Dvec,
       const float* __restrict__ Wdt, const float* __restrict__ bdt) {
    __shared__ float sB[CH][16], sC[CH][16];
    __shared__ float sX[CH][16], sZ[CH][16], sDT[CH][16];
    __shared__ float sP[CH][16 * PSTRIDE];
    const int tid = threadIdx.x;
    const int dd = tid >> 4, n = tid & 15;
    const int b = blockIdx.y;
    const int d0 = blockIdx.x * 16;

    const float a  = -__expf(A_log[(d0 + dd) * DSTATE + n]);
    const float wq = Wdt[d0 + n];
    const float bq = bdt[d0 + n];
    const float Dq = Dvec[d0 + n];
    float h = 0.f;

    for (int c = 0; c < SEQL / CH; c++) {
        const int tok0 = b * SEQL + c * CH;
        for (int i = tid; i < CH * 33; i += 256) {
            int tt = i / 33, e = i - tt * 33;
            float v = g_dbc[(size_t)(tok0 + tt) * 33 + e];
            if (e >= 17)     sC[tt][e - 17] = v;
            else if (e >= 1) sB[tt][e - 1]  = v;
        }
        for (int i = tid; i < CH * 16; i += 256) {
            int tt = i >> 4;
            sX[tt][n] = g_xi[(size_t)(tok0 + tt) * DINNER + d0 + n];
            sZ[tt][n] = g_xz[(size_t)(tok0 + tt) * (2 * DINNER) + DINNER + d0 + n];
            float u = g_dbc[(size_t)(tok0 + tt) * 33] * wq + bq;
            sDT[tt][n] = (u > 20.f) ? u : log1pf(__expf(u));
        }
        __syncthreads();
#pragma unroll
        for (int t = 0; t < CH; t++) {
            float dtv = sDT[t][dd];
            float xv  = sX[t][dd];
            float dA  = __expf(dtv * a);
            h = dA * h + (dtv * sB[t][n]) * xv;
            sP[t][dd * PSTRIDE + n] = h * sC[t][n];
        }
        __syncthreads();
        for (int i = tid; i < CH * 16; i += 256) {
            int tt = i >> 4;
            float s = 0.f;
#pragma unroll
            for (int j = 0; j < 16; j++) s += sP[tt][n * PSTRIDE + j];
            float xv = sX[tt][n], zv = sZ[tt][n];
            float yv = (s + Dq * xv) * (zv / (1.f + __expf(-zv)));
            g_y[(size_t)(tok0 + tt) * DINNER + d0 + n] = __uint_as_float(f2tf32(yv));
        }
        __syncthreads();
    }
}

// ---------------------------------------------------------------------------
extern "C" void kernel_launch(void* const* d_in, const int* in_sizes, int n_in,
                              void* d_out, int out_size) {
    const float* x     = (const float*)d_in[0];
    const float* W_in  = (const float*)d_in[1];
    const float* convw = (const float*)d_in[2];
    const float* convb = (const float*)d_in[3];
    const float* W_x   = (const float*)d_in[4];
    const float* W_dt  = (const float*)d_in[5];
    const float* b_dt  = (const float*)d_in[6];
    const float* A_log = (const float*)d_in[7];
    const float* Dv    = (const float*)d_in[8];
    const float* W_out = (const float*)d_in[9];
    float* out = (float*)d_out;

    float *xz, *y, *xr, *wr, *wor;
    cudaGetSymbolAddress((void**)&xz,  g_xz);
    cudaGetSymbolAddress((void**)&y,   g_y);
    cudaGetSymbolAddress((void**)&xr,  g_xr);
    cudaGetSymbolAddress((void**)&wr,  g_wr);
    cudaGetSymbolAddress((void**)&wor, g_wor);

    cudaFuncSetAttribute(tf32_gemm_nt, cudaFuncAttributeMaxDynamicSharedMemorySize, GEMM_SMEM);

    // 0) rna-round GEMM operands (so GEMM needs no in-kernel cvt)
    round_k<<<(TOKENS * DMODEL / 4 + 255) / 256, 256>>>(x, xr, TOKENS * DMODEL / 4);
    round_k<<<(2 * DINNER * DMODEL / 4 + 255) / 256, 256>>>(W_in, wr, 2 * DINNER * DMODEL / 4);
    round_k<<<(DMODEL * DINNER / 4 + 255) / 256, 256>>>(W_out, wor, DMODEL * DINNER / 4);

    // 1) xz = x @ W_in^T   [4096 x 4096], K=1024
    tf32_gemm_nt<<<dim3(4096 / BN, TOKENS / BM), 256, GEMM_SMEM>>>(xr, wr, xz, TOKENS, 4096, DMODEL);

    // 2) causal depthwise conv + silu -> g_xi
    conv_silu_k<<<(TOKENS * DINNER) / 256, 256>>>(convw, convb);

    // 3) x_dbl = xi @ W_x^T (split-K + deterministic reduce)
    xdbl_part_k<<<dim3(TOKENS / 64, 8), dim3(33, 8)>>>(W_x);
    xdbl_reduce_k<<<(TOKENS * 33 + 255) / 256, 256>>>();

    // 4) selective scan -> g_y (tf32-rounded)
    scan_k<<<dim3(DINNER / 16, 2), 256>>>(A_log, Dv, W_dt, b_dt);

    // 5) out = y @ W_out^T   [4096 x 1024], K=2048
    tf32_gemm_nt<<<dim3(DMODEL / BN, TOKENS / BM), 256, GEMM_SMEM>>>(y, wor, out, TOKENS, DMODEL, DINNER);
}

// round 6
// speedup vs baseline: 1.2421x; 1.2421x over previous
#include <cuda_runtime.h>
#include <cuda_fp16.h>
#include <math.h>
#include <stdint.h>

#define TOKENS 4096
#define DMODEL 1024
#define DINNER 2048
#define DSTATE 16
#define SEQL   2048

// Scratch (static device globals — no runtime allocation allowed)
__device__ __align__(256) float  g_xz [TOKENS * 2 * DINNER];  // GEMM1 out: xi-preconv | z
__device__ __align__(256) float  g_xi [TOKENS * DINNER];      // conv+silu output (fp32)
__device__ __align__(256) float  g_dbc[TOKENS * 33];
__device__ __align__(256) float  g_dbcp[8][TOKENS * 33];
__device__ __align__(256) __half g_xh [TOKENS * DMODEL];      // half x
__device__ __align__(256) __half g_wh [2 * DINNER * DMODEL];  // half W_in
__device__ __align__(256) __half g_woh[DMODEL * DINNER];      // half W_out
__device__ __align__(256) __half g_yh [TOKENS * DINNER];      // half scan output

// ---------------------------------------------------------------------------
__device__ __forceinline__ void cp_async16(void* smem_dst, const void* gmem_src) {
    uint32_t s = (uint32_t)__cvta_generic_to_shared(smem_dst);
    asm volatile("cp.async.cg.shared.global [%0], [%1], 16;" :: "r"(s), "l"(gmem_src));
}

__device__ __forceinline__ void mma_f16(float* c, const uint32_t* a, const uint32_t* b) {
    asm volatile(
        "mma.sync.aligned.m16n8k16.row.col.f32.f16.f16.f32 "
        "{%0,%1,%2,%3}, {%4,%5,%6,%7}, {%8,%9}, {%0,%1,%2,%3};"
        : "+f"(c[0]), "+f"(c[1]), "+f"(c[2]), "+f"(c[3])
        : "r"(a[0]), "r"(a[1]), "r"(a[2]), "r"(a[3]), "r"(b[0]), "r"(b[1]));
}

// ---------------------------------------------------------------------------
// FP16 mma.sync GEMM: C[M,N] = A[M,K]h * B[N,K]h^T, fp32 accum.
// BM=128, BK=64, BNT template (256 or 128). 8 warps (2 x 4).
// smem rows padded to 72 halfs (conflict-free fragment LDS). 3-stage cp.async.
// ---------------------------------------------------------------------------
#define BM 128
#define BK 64
#define STRH 72                              // halfs per smem row

template <int BNT>
__global__ void __launch_bounds__(256, BNT == 128 ? 2 : 1)
h_gemm_nt(const __half* __restrict__ A, const __half* __restrict__ B,
          float* __restrict__ C, int M, int N, int K) {
    extern __shared__ __half sh[];
    constexpr int A_HALFS = BM * STRH;
    constexpr int B_HALFS = BNT * STRH;
    constexpr int STG_HALFS = A_HALFS + B_HALFS;
    constexpr int WN = BNT / 4;              // warp-tile N
    constexpr int NFN = WN / 8;              // b frags per warp

    const int tid  = threadIdx.x;
    const int wid  = tid >> 5;
    const int lane = tid & 31;
    const int gid  = lane >> 2;              // 0..7
    const int t4   = lane & 3;               // 0..3
    const int wm   = wid & 1;                // 64 rows each
    const int wn   = wid >> 1;               // WN cols each
    const int row0 = blockIdx.y * BM;
    const int col0 = blockIdx.x * BNT;

    // loader: 16B granules; granule g -> row g>>3, chunk g&7 (8 halfs)
    const int lrow = tid >> 3;               // 0..31
    const int lchk = (tid & 7) * 8;          // half offset 0..56

    float acc[4][NFN][4] = {};
    const int niter = K / BK;

    auto load_stage = [&](int stage, int k0) {
        __half* Sa = sh + stage * STG_HALFS;
        __half* Sb = Sa + A_HALFS;
#pragma unroll
        for (int i = 0; i < BM / 32; i++) {
            int r = lrow + i * 32;
            cp_async16(&Sa[r * STRH + lchk], A + (size_t)(row0 + r) * K + k0 + lchk);
        }
#pragma unroll
        for (int i = 0; i < BNT / 32; i++) {
            int r = lrow + i * 32;
            cp_async16(&Sb[r * STRH + lchk], B + (size_t)(col0 + r) * K + k0 + lchk);
        }
    };

    load_stage(0, 0);
    asm volatile("cp.async.commit_group;");
    if (niter > 1) load_stage(1, BK);
    asm volatile("cp.async.commit_group;");

    int s = 0;
    for (int it = 0; it < niter; it++) {
        asm volatile("cp.async.wait_group 1;");
        __syncthreads();

        if (it + 2 < niter) load_stage((it + 2) % 3, (it + 2) * BK);
        asm volatile("cp.async.commit_group;");

        const __half* Ab = sh + s * STG_HALFS;
        const __half* Bb = Ab + A_HALFS;
#pragma unroll
        for (int kk = 0; kk < BK / 16; kk++) {
            const int kb = kk * 16 + 2 * t4;
            uint32_t af[4][4], bf[NFN][2];
#pragma unroll
            for (int fm = 0; fm < 4; fm++) {
                int r = wm * 64 + fm * 16 + gid;
                af[fm][0] = *(const uint32_t*)&Ab[r * STRH + kb];
                af[fm][1] = *(const uint32_t*)&Ab[(r + 8) * STRH + kb];
                af[fm][2] = *(const uint32_t*)&Ab[r * STRH + kb + 8];
                af[fm][3] = *(const uint32_t*)&Ab[(r + 8) * STRH + kb + 8];
            }
#pragma unroll
            for (int fn = 0; fn < NFN; fn++) {
                int nn = wn * WN + fn * 8 + gid;
                bf[fn][0] = *(const uint32_t*)&Bb[nn * STRH + kb];
                bf[fn][1] = *(const uint32_t*)&Bb[nn * STRH + kb + 8];
            }
#pragma unroll
            for (int fm = 0; fm < 4; fm++)
#pragma unroll
                for (int fn = 0; fn < NFN; fn++)
                    mma_f16(acc[fm][fn], af[fm], bf[fn]);
        }
        __syncthreads();
        s = (s + 1) % 3;
    }

#pragma unroll
    for (int fm = 0; fm < 4; fm++) {
        int r = row0 + wm * 64 + fm * 16 + gid;
#pragma unroll
        for (int fn = 0; fn < NFN; fn++) {
            int cbase = col0 + wn * WN + fn * 8 + t4 * 2;
            float2* p0 = (float2*)&C[(size_t)r * N + cbase];
            float2* p1 = (float2*)&C[(size_t)(r + 8) * N + cbase];
            *p0 = make_float2(acc[fm][fn][0], acc[fm][fn][1]);
            *p1 = make_float2(acc[fm][fn][2], acc[fm][fn][3]);
        }
    }
}

// ---------------------------------------------------------------------------
// fp32 -> fp16 conversion (GEMM operand prep), 8 elems/thread
// ---------------------------------------------------------------------------
__global__ void cvt_h(const float* __restrict__ in, __half* __restrict__ out, int n8) {
    int i = blockIdx.x * blockDim.x + threadIdx.x;
    if (i >= n8) return;
    float4 v0 = ((const float4*)in)[2 * i];
    float4 v1 = ((const float4*)in)[2 * i + 1];
    __half2 h[4];
    h[0] = __float22half2_rn(make_float2(v0.x, v0.y));
    h[1] = __float22half2_rn(make_float2(v0.z, v0.w));
    h[2] = __float22half2_rn(make_float2(v1.x, v1.y));
    h[3] = __float22half2_rn(make_float2(v1.z, v1.w));
    ((uint4*)out)[i] = *(uint4*)h;
}

// ---------------------------------------------------------------------------
// Causal depthwise conv (width 4) + bias + SiLU on first half of xz -> g_xi
// ---------------------------------------------------------------------------
__global__ void conv_silu_k(const float* __restrict__ cw, const float* __restrict__ cb) {
    int idx = blockIdx.x * blockDim.x + threadIdx.x;
    int d = idx & (DINNER - 1);
    int t = idx >> 11;
    int l = t & (SEQL - 1);
    float w0 = cw[d * 4 + 0], w1 = cw[d * 4 + 1], w2 = cw[d * 4 + 2], w3 = cw[d * 4 + 3];
    float acc = cb[d];
    size_t base = (size_t)t * (2 * DINNER) + d;
    if (l >= 3) acc += g_xz[base - 3 * (size_t)(2 * DINNER)] * w0;
    if (l >= 2) acc += g_xz[base - 2 * (size_t)(2 * DINNER)] * w1;
    if (l >= 1) acc += g_xz[base - 1 * (size_t)(2 * DINNER)] * w2;
    acc += g_xz[base] * w3;
    g_xi[idx] = acc / (1.f + __expf(-acc));
}

// ---------------------------------------------------------------------------
// x_dbl split-K partials + deterministic reduce (fp32)
// ---------------------------------------------------------------------------
__global__ void xdbl_part_k(const float* __restrict__ Wx) {
    __shared__ float Xs[64][33];
    __shared__ float Ws[33][33];
    const int tx = threadIdx.x, ty = threadIdx.y;   // (33,8)
    const int tid = ty * 33 + tx;
    const int tok0 = blockIdx.x * 64;
    const int kbase = blockIdx.y * 256;
    float acc[8] = {};
    for (int k0 = kbase; k0 < kbase + 256; k0 += 32) {
        for (int i = tid; i < 64 * 32; i += 264) {
            int tt = i >> 5, kk = i & 31;
            Xs[tt][kk] = g_xi[(size_t)(tok0 + tt) * DINNER + k0 + kk];
        }
        for (int i = tid; i < 33 * 32; i += 264) {
            int e = i >> 5, kk = i & 31;
            Ws[e][kk] = Wx[(size_t)e * DINNER + k0 + kk];
        }
        __syncthreads();
#pragma unroll
        for (int kk = 0; kk < 32; kk++) {
            float w = Ws[tx][kk];
#pragma unroll
            for (int i = 0; i < 8; i++)
                acc[i] += Xs[ty * 8 + i][kk] * w;
        }
        __syncthreads();
    }
#pragma unroll
    for (int i = 0; i < 8; i++)
        g_dbcp[blockIdx.y][(size_t)(tok0 + ty * 8 + i) * 33 + tx] = acc[i];
}

__global__ void xdbl_reduce_k() {
    int i = blockIdx.x * blockDim.x + threadIdx.x;
    if (i >= TOKENS * 33) return;
    float s = 0.f;
#pragma unroll
    for (int p = 0; p < 8; p++) s += g_dbcp[p][i];
    g_dbc[i] = s;
}

// ---------------------------------------------------------------------------
// Selective scan: 8 channels/block (128 thr), grid (256, 2) = 512 blocks.
// softplus fused in staging; +D*xi; *silu(z); writes half y for GEMM2.
// ---------------------------------------------------------------------------
#define CH 32
#define CPB 8
#define PSTRIDE 17

__global__ void __launch_bounds__(128)
scan_k(const float* __restrict__ A_log, const float* __restrict__ Dvec,
       const float* __restrict__ Wdt, const float* __restrict__ bdt) {
    __shared__ float sB[CH][16], sC[CH][16];
    __shared__ float sX[CH][CPB], sZ[CH][CPB], sDT[CH][CPB];
    __shared__ float sP[CH][CPB * PSTRIDE];
    const int tid = threadIdx.x;              // 128
    const int dd = tid >> 4, n = tid & 15;    // channel 0..7, state 0..15
    const int q8 = tid & 7;                   // channel index for IO phases
    const int b = blockIdx.y;
    const int d0 = blockIdx.x * CPB;

    const float a  = -__expf(A_log[(d0 + dd) * DSTATE + n]);
    const float wq = Wdt[d0 + q8];
    const float bq = bdt[d0 + q8];
    const float Dq = Dvec[d0 + q8];
    float h = 0.f;

    for (int c = 0; c < SEQL / CH; c++) {
        const int tok0 = b * SEQL + c * CH;
        for (int i = tid; i < CH * 33; i += 128) {
            int tt = i / 33, e = i - tt * 33;
            float v = g_dbc[(size_t)(tok0 + tt) * 33 + e];
            if (e >= 17)     sC[tt][e - 17] = v;
            else if (e >= 1) sB[tt][e - 1]  = v;
        }
        for (int i = tid; i < CH * CPB; i += 128) {
            int tt = i >> 3;                  // q == q8 (128 % 8 == 0)
            sX[tt][q8] = g_xi[(size_t)(tok0 + tt) * DINNER + d0 + q8];
            sZ[tt][q8] = g_xz[(size_t)(tok0 + tt) * (2 * DINNER) + DINNER + d0 + q8];
            float u = g_dbc[(size_t)(tok0 + tt) * 33] * wq + bq;
            sDT[tt][q8] = (u > 20.f) ? u : log1pf(__expf(u));
        }
        __syncthreads();
#pragma unroll
        for (int t = 0; t < CH; t++) {
            float dtv = sDT[t][dd];
            float xv  = sX[t][dd];
            float dA  = __expf(dtv * a);
            h = dA * h + (dtv * sB[t][n]) * xv;
            sP[t][dd * PSTRIDE + n] = h * sC[t][n];
        }
        __syncthreads();
        for (int i = tid; i < CH * CPB; i += 128) {
            int tt = i >> 3;
            float s = 0.f;
#pragma unroll
            for (int j = 0; j < 16; j++) s += sP[tt][q8 * PSTRIDE + j];
            float xv = sX[tt][q8], zv = sZ[tt][q8];
            float yv = (s + Dq * xv) * (zv / (1.f + __expf(-zv)));
            g_yh[(size_t)(tok0 + tt) * DINNER + d0 + q8] = __float2half_rn(yv);
        }
        __syncthreads();
    }
}

// ---------------------------------------------------------------------------
extern "C" void kernel_launch(void* const* d_in, const int* in_sizes, int n_in,
                              void* d_out, int out_size) {
    const float* x     = (const float*)d_in[0];
    const float* W_in  = (const float*)d_in[1];
    const float* convw = (const float*)d_in[2];
    const float* convb = (const float*)d_in[3];
    const float* W_x   = (const float*)d_in[4];
    const float* W_dt  = (const float*)d_in[5];
    const float* b_dt  = (const float*)d_in[6];
    const float* A_log = (const float*)d_in[7];
    const float* Dv    = (const float*)d_in[8];
    const float* W_out = (const float*)d_in[9];
    float* out = (float*)d_out;

    float *xz;
    __half *xh, *wh, *woh, *yh;
    cudaGetSymbolAddress((void**)&xz,  g_xz);
    cudaGetSymbolAddress((void**)&xh,  g_xh);
    cudaGetSymbolAddress((void**)&wh,  g_wh);
    cudaGetSymbolAddress((void**)&woh, g_woh);
    cudaGetSymbolAddress((void**)&yh,  g_yh);

    const int smem1 = 3 * (BM + 256) * STRH * 2;   // 165888 B
    const int smem2 = 3 * (BM + 128) * STRH * 2;   // 110592 B
    cudaFuncSetAttribute(h_gemm_nt<256>, cudaFuncAttributeMaxDynamicSharedMemorySize, smem1);
    cudaFuncSetAttribute(h_gemm_nt<128>, cudaFuncAttributeMaxDynamicSharedMemorySize, smem2);

    // 0) convert GEMM operands to fp16
    cvt_h<<<(TOKENS * DMODEL / 8 + 255) / 256, 256>>>(x, xh, TOKENS * DMODEL / 8);
    cvt_h<<<(2 * DINNER * DMODEL / 8 + 255) / 256, 256>>>(W_in, wh, 2 * DINNER * DMODEL / 8);
    cvt_h<<<(DMODEL * DINNER / 8 + 255) / 256, 256>>>(W_out, woh, DMODEL * DINNER / 8);

    // 1) xz = x @ W_in^T   [4096 x 4096], K=1024   (profiled launch, index 3)
    h_gemm_nt<256><<<dim3(4096 / 256, TOKENS / BM), 256, smem1>>>(xh, wh, xz, TOKENS, 4096, DMODEL);

    // 2) causal depthwise conv + silu -> g_xi
    conv_silu_k<<<(TOKENS * DINNER) / 256, 256>>>(convw, convb);

    // 3) x_dbl = xi @ W_x^T (split-K + deterministic reduce)
    xdbl_part_k<<<dim3(TOKENS / 64, 8), dim3(33, 8)>>>(W_x);
    xdbl_reduce_k<<<(TOKENS * 33 + 255) / 256, 256>>>();

    // 4) selective scan -> g_yh (half)
    scan_k<<<dim3(DINNER / CPB, 2), 128>>>(A_log, Dv, W_dt, b_dt);

    // 5) out = y @ W_out^T   [4096 x 1024], K=2048
    h_gemm_nt<128><<<dim3(DMODEL / 128, TOKENS / BM), 256, smem2>>>(yh, woh, out, TOKENS, DMODEL, DINNER);
}

// round 7
// speedup vs baseline: 1.2593x; 1.0138x over previous
#include <cuda_runtime.h>
#include <cuda_fp16.h>
#include <math.h>
#include <stdint.h>

#define TOKENS 4096
#define DMODEL 1024
#define DINNER 2048
#define DSTATE 16
#define SEQL   2048

// Scratch (static device globals — no runtime allocation allowed)
__device__ __align__(256) float  g_xz [TOKENS * 2 * DINNER];  // GEMM1 out: xi-preconv | z
__device__ __align__(256) float  g_xi [TOKENS * DINNER];      // conv+silu output (fp32)
__device__ __align__(256) float  g_dbc[TOKENS * 33];
__device__ __align__(256) float  g_dbcp[8][TOKENS * 33];
__device__ __align__(256) __half g_xh [TOKENS * DMODEL];      // half x
__device__ __align__(256) __half g_wh [2 * DINNER * DMODEL];  // half W_in
__device__ __align__(256) __half g_woh[DMODEL * DINNER];      // half W_out
__device__ __align__(256) __half g_yh [TOKENS * DINNER];      // half scan output

// ---------------------------------------------------------------------------
__device__ __forceinline__ void cp_async16(void* smem_dst, const void* gmem_src) {
    uint32_t s = (uint32_t)__cvta_generic_to_shared(smem_dst);
    asm volatile("cp.async.cg.shared.global [%0], [%1], 16;" :: "r"(s), "l"(gmem_src));
}

__device__ __forceinline__ void mma_f16(float* c, const uint32_t* a, const uint32_t* b) {
    asm volatile(
        "mma.sync.aligned.m16n8k16.row.col.f32.f16.f16.f32 "
        "{%0,%1,%2,%3}, {%4,%5,%6,%7}, {%8,%9}, {%0,%1,%2,%3};"
        : "+f"(c[0]), "+f"(c[1]), "+f"(c[2]), "+f"(c[3])
        : "r"(a[0]), "r"(a[1]), "r"(a[2]), "r"(a[3]), "r"(b[0]), "r"(b[1]));
}

__device__ __forceinline__ void ldsm_x4(uint32_t& r0, uint32_t& r1, uint32_t& r2,
                                        uint32_t& r3, uint32_t saddr) {
    asm volatile("ldmatrix.sync.aligned.m8n8.x4.shared.b16 {%0,%1,%2,%3}, [%4];"
        : "=r"(r0), "=r"(r1), "=r"(r2), "=r"(r3) : "r"(saddr));
}

// ---------------------------------------------------------------------------
// FP16 mma.sync GEMM with ldmatrix: C[M,N] = A[M,K]h * B[N,K]h^T, fp32 accum.
// BM=128, BK=64, BNT template (256/128). 8 warps (2 x 4), 3-stage cp.async.
// smem rows padded to 72 halfs (conflict-free for both cp.async and LDSM).
// ---------------------------------------------------------------------------
#define BM 128
#define BK 64
#define STRH 72                              // halfs per smem row

template <int BNT>
__global__ void __launch_bounds__(256, BNT == 128 ? 2 : 1)
h_gemm_nt(const __half* __restrict__ A, const __half* __restrict__ B,
          float* __restrict__ C, int M, int N, int K) {
    extern __shared__ __half sh[];
    constexpr int A_HALFS = BM * STRH;
    constexpr int B_HALFS = BNT * STRH;
    constexpr int STG_HALFS = A_HALFS + B_HALFS;
    constexpr int WN = BNT / 4;              // warp-tile N
    constexpr int NFN = WN / 8;              // b frags per warp
    constexpr int NPAIR = NFN / 2;           // ldmatrix pairs for B

    const int tid  = threadIdx.x;
    const int wid  = tid >> 5;
    const int lane = tid & 31;
    const int gid  = lane >> 2;              // 0..7
    const int t4   = lane & 3;               // 0..3
    const int wm   = wid & 1;                // 64 rows each
    const int wn   = wid >> 1;               // WN cols each
    const int row0 = blockIdx.y * BM;
    const int col0 = blockIdx.x * BNT;

    const uint32_t sbase = (uint32_t)__cvta_generic_to_shared(sh);

    // ldmatrix lane->row mappings
    const int a_row  = wm * 64 + (lane & 15);        // + fm*16
    const int a_colh = (lane >> 4) * 8;              // k-half select
    const int b_row  = (lane & 7) + ((lane >> 4) * 8);   // within 16-row pair group
    const int b_colh = ((lane >> 3) & 1) * 8;

    // loader: 16B granules
    const int lrow = tid >> 3;               // 0..31
    const int lchk = (tid & 7) * 8;          // half offset 0..56

    float acc[4][NFN][4] = {};
    const int niter = K / BK;

    auto load_stage = [&](int stage, int k0) {
        __half* Sa = sh + stage * STG_HALFS;
        __half* Sb = Sa + A_HALFS;
#pragma unroll
        for (int i = 0; i < BM / 32; i++) {
            int r = lrow + i * 32;
            cp_async16(&Sa[r * STRH + lchk], A + (size_t)(row0 + r) * K + k0 + lchk);
        }
#pragma unroll
        for (int i = 0; i < BNT / 32; i++) {
            int r = lrow + i * 32;
            cp_async16(&Sb[r * STRH + lchk], B + (size_t)(col0 + r) * K + k0 + lchk);
        }
    };

    load_stage(0, 0);
    asm volatile("cp.async.commit_group;");
    if (niter > 1) load_stage(1, BK);
    asm volatile("cp.async.commit_group;");

    int s = 0;
    for (int it = 0; it < niter; it++) {
        asm volatile("cp.async.wait_group 1;");
        __syncthreads();

        if (it + 2 < niter) load_stage((it + 2) % 3, (it + 2) * BK);
        asm volatile("cp.async.commit_group;");

        const uint32_t sA = sbase + (uint32_t)(s * STG_HALFS) * 2;
        const uint32_t sB = sA + A_HALFS * 2;
#pragma unroll
        for (int kk = 0; kk < BK / 16; kk++) {
            const int kb = kk * 16;
            uint32_t af[4][4], bf[NFN][2];
#pragma unroll
            for (int fm = 0; fm < 4; fm++)
                ldsm_x4(af[fm][0], af[fm][1], af[fm][2], af[fm][3],
                        sA + (uint32_t)((a_row + fm * 16) * STRH + kb + a_colh) * 2);
#pragma unroll
            for (int p = 0; p < NPAIR; p++)
                ldsm_x4(bf[2 * p][0], bf[2 * p][1], bf[2 * p + 1][0], bf[2 * p + 1][1],
                        sB + (uint32_t)((wn * WN + p * 16 + b_row) * STRH + kb + b_colh) * 2);
#pragma unroll
            for (int fm = 0; fm < 4; fm++)
#pragma unroll
                for (int fn = 0; fn < NFN; fn++)
                    mma_f16(acc[fm][fn], af[fm], bf[fn]);
        }
        __syncthreads();
        s = (s + 1) % 3;
    }

#pragma unroll
    for (int fm = 0; fm < 4; fm++) {
        int r = row0 + wm * 64 + fm * 16 + gid;
#pragma unroll
        for (int fn = 0; fn < NFN; fn++) {
            int cbase = col0 + wn * WN + fn * 8 + t4 * 2;
            float2* p0 = (float2*)&C[(size_t)r * N + cbase];
            float2* p1 = (float2*)&C[(size_t)(r + 8) * N + cbase];
            *p0 = make_float2(acc[fm][fn][0], acc[fm][fn][1]);
            *p1 = make_float2(acc[fm][fn][2], acc[fm][fn][3]);
        }
    }
}

// ---------------------------------------------------------------------------
// fp32 -> fp16 conversion (GEMM operand prep), 8 elems/thread
// ---------------------------------------------------------------------------
__global__ void cvt_h(const float* __restrict__ in, __half* __restrict__ out, int n8) {
    int i = blockIdx.x * blockDim.x + threadIdx.x;
    if (i >= n8) return;
    float4 v0 = ((const float4*)in)[2 * i];
    float4 v1 = ((const float4*)in)[2 * i + 1];
    __half2 h[4];
    h[0] = __float22half2_rn(make_float2(v0.x, v0.y));
    h[1] = __float22half2_rn(make_float2(v0.z, v0.w));
    h[2] = __float22half2_rn(make_float2(v1.x, v1.y));
    h[3] = __float22half2_rn(make_float2(v1.z, v1.w));
    ((uint4*)out)[i] = *(uint4*)h;
}

// ---------------------------------------------------------------------------
// Causal depthwise conv (width 4) + bias + SiLU on first half of xz -> g_xi
// ---------------------------------------------------------------------------
__global__ void conv_silu_k(const float* __restrict__ cw, const float* __restrict__ cb) {
    int idx = blockIdx.x * blockDim.x + threadIdx.x;
    int d = idx & (DINNER - 1);
    int t = idx >> 11;
    int l = t & (SEQL - 1);
    float w0 = cw[d * 4 + 0], w1 = cw[d * 4 + 1], w2 = cw[d * 4 + 2], w3 = cw[d * 4 + 3];
    float acc = cb[d];
    size_t base = (size_t)t * (2 * DINNER) + d;
    if (l >= 3) acc += g_xz[base - 3 * (size_t)(2 * DINNER)] * w0;
    if (l >= 2) acc += g_xz[base - 2 * (size_t)(2 * DINNER)] * w1;
    if (l >= 1) acc += g_xz[base - 1 * (size_t)(2 * DINNER)] * w2;
    acc += g_xz[base] * w3;
    g_xi[idx] = acc / (1.f + __expf(-acc));
}

// ---------------------------------------------------------------------------
// x_dbl split-K partials + deterministic reduce (fp32)
// ---------------------------------------------------------------------------
__global__ void xdbl_part_k(const float* __restrict__ Wx) {
    __shared__ float Xs[64][33];
    __shared__ float Ws[33][33];
    const int tx = threadIdx.x, ty = threadIdx.y;   // (33,8)
    const int tid = ty * 33 + tx;
    const int tok0 = blockIdx.x * 64;
    const int kbase = blockIdx.y * 256;
    float acc[8] = {};
    for (int k0 = kbase; k0 < kbase + 256; k0 += 32) {
        for (int i = tid; i < 64 * 32; i += 264) {
            int tt = i >> 5, kk = i & 31;
            Xs[tt][kk] = g_xi[(size_t)(tok0 + tt) * DINNER + k0 + kk];
        }
        for (int i = tid; i < 33 * 32; i += 264) {
            int e = i >> 5, kk = i & 31;
            Ws[e][kk] = Wx[(size_t)e * DINNER + k0 + kk];
        }
        __syncthreads();
#pragma unroll
        for (int kk = 0; kk < 32; kk++) {
            float w = Ws[tx][kk];
#pragma unroll
            for (int i = 0; i < 8; i++)
                acc[i] += Xs[ty * 8 + i][kk] * w;
        }
        __syncthreads();
    }
#pragma unroll
    for (int i = 0; i < 8; i++)
        g_dbcp[blockIdx.y][(size_t)(tok0 + ty * 8 + i) * 33 + tx] = acc[i];
}

__global__ void xdbl_reduce_k() {
    int i = blockIdx.x * blockDim.x + threadIdx.x;
    if (i >= TOKENS * 33) return;
    float s = 0.f;
#pragma unroll
    for (int p = 0; p < 8; p++) s += g_dbcp[p][i];
    g_dbc[i] = s;
}

// ---------------------------------------------------------------------------
// Selective scan: 8 channels/block (128 thr), grid (256, 2) = 512 blocks.
// ---------------------------------------------------------------------------
#define CH 32
#define CPB 8
#define PSTRIDE 17

__global__ void __launch_bounds__(128)
scan_k(const float* __restrict__ A_log, const float* __restrict__ Dvec,
       const float* __restrict__ Wdt, const float* __restrict__ bdt) {
    __shared__ float sB[CH][16], sC[CH][16];
    __shared__ float sX[CH][CPB], sZ[CH][CPB], sDT[CH][CPB];
    __shared__ float sP[CH][CPB * PSTRIDE];
    const int tid = threadIdx.x;              // 128
    const int dd = tid >> 4, n = tid & 15;    // channel 0..7, state 0..15
    const int q8 = tid & 7;                   // channel index for IO phases
    const int b = blockIdx.y;
    const int d0 = blockIdx.x * CPB;

    const float a  = -__expf(A_log[(d0 + dd) * DSTATE + n]);
    const float wq = Wdt[d0 + q8];
    const float bq = bdt[d0 + q8];
    const float Dq = Dvec[d0 + q8];
    float h = 0.f;

    for (int c = 0; c < SEQL / CH; c++) {
        const int tok0 = b * SEQL + c * CH;
        for (int i = tid; i < CH * 33; i += 128) {
            int tt = i / 33, e = i - tt * 33;
            float v = g_dbc[(size_t)(tok0 + tt) * 33 + e];
            if (e >= 17)     sC[tt][e - 17] = v;
            else if (e >= 1) sB[tt][e - 1]  = v;
        }
        for (int i = tid; i < CH * CPB; i += 128) {
            int tt = i >> 3;
            sX[tt][q8] = g_xi[(size_t)(tok0 + tt) * DINNER + d0 + q8];
            sZ[tt][q8] = g_xz[(size_t)(tok0 + tt) * (2 * DINNER) + DINNER + d0 + q8];
            float u = g_dbc[(size_t)(tok0 + tt) * 33] * wq + bq;
            sDT[tt][q8] = (u > 20.f) ? u : log1pf(__expf(u));
        }
        __syncthreads();
#pragma unroll
        for (int t = 0; t < CH; t++) {
            float dtv = sDT[t][dd];
            float xv  = sX[t][dd];
            float dA  = __expf(dtv * a);
            h = dA * h + (dtv * sB[t][n]) * xv;
            sP[t][dd * PSTRIDE + n] = h * sC[t][n];
        }
        __syncthreads();
        for (int i = tid; i < CH * CPB; i += 128) {
            int tt = i >> 3;
            float s = 0.f;
#pragma unroll
            for (int j = 0; j < 16; j++) s += sP[tt][q8 * PSTRIDE + j];
            float xv = sX[tt][q8], zv = sZ[tt][q8];
            float yv = (s + Dq * xv) * (zv / (1.f + __expf(-zv)));
            g_yh[(size_t)(tok0 + tt) * DINNER + d0 + q8] = __float2half_rn(yv);
        }
        __syncthreads();
    }
}

// ---------------------------------------------------------------------------
extern "C" void kernel_launch(void* const* d_in, const int* in_sizes, int n_in,
                              void* d_out, int out_size) {
    const float* x     = (const float*)d_in[0];
    const float* W_in  = (const float*)d_in[1];
    const float* convw = (const float*)d_in[2];
    const float* convb = (const float*)d_in[3];
    const float* W_x   = (const float*)d_in[4];
    const float* W_dt  = (const float*)d_in[5];
    const float* b_dt  = (const float*)d_in[6];
    const float* A_log = (const float*)d_in[7];
    const float* Dv    = (const float*)d_in[8];
    const float* W_out = (const float*)d_in[9];
    float* out = (float*)d_out;

    float *xz;
    __half *xh, *wh, *woh, *yh;
    cudaGetSymbolAddress((void**)&xz,  g_xz);
    cudaGetSymbolAddress((void**)&xh,  g_xh);
    cudaGetSymbolAddress((void**)&wh,  g_wh);
    cudaGetSymbolAddress((void**)&woh, g_woh);
    cudaGetSymbolAddress((void**)&yh,  g_yh);

    const int smem1 = 3 * (BM + 256) * STRH * 2;   // 165888 B
    const int smem2 = 3 * (BM + 128) * STRH * 2;   // 110592 B
    cudaFuncSetAttribute(h_gemm_nt<256>, cudaFuncAttributeMaxDynamicSharedMemorySize, smem1);
    cudaFuncSetAttribute(h_gemm_nt<128>, cudaFuncAttributeMaxDynamicSharedMemorySize, smem2);

    // 0) convert GEMM operands to fp16
    cvt_h<<<(TOKENS * DMODEL / 8 + 255) / 256, 256>>>(x, xh, TOKENS * DMODEL / 8);
    cvt_h<<<(2 * DINNER * DMODEL / 8 + 255) / 256, 256>>>(W_in, wh, 2 * DINNER * DMODEL / 8);
    cvt_h<<<(DMODEL * DINNER / 8 + 255) / 256, 256>>>(W_out, woh, DMODEL * DINNER / 8);

    // 1) xz = x @ W_in^T   [4096 x 4096], K=1024
    h_gemm_nt<256><<<dim3(4096 / 256, TOKENS / BM), 256, smem1>>>(xh, wh, xz, TOKENS, 4096, DMODEL);

    // 2) causal depthwise conv + silu -> g_xi
    conv_silu_k<<<(TOKENS * DINNER) / 256, 256>>>(convw, convb);

    // 3) x_dbl = xi @ W_x^T (split-K + deterministic reduce)
    xdbl_part_k<<<dim3(TOKENS / 64, 8), dim3(33, 8)>>>(W_x);
    xdbl_reduce_k<<<(TOKENS * 33 + 255) / 256, 256>>>();

    // 4) selective scan -> g_yh (half)
    scan_k<<<dim3(DINNER / CPB, 2), 128>>>(A_log, Dv, W_dt, b_dt);

    // 5) out = y @ W_out^T   [4096 x 1024], K=2048
    h_gemm_nt<128><<<dim3(DMODEL / 128, TOKENS / BM), 256, smem2>>>(yh, woh, out, TOKENS, DMODEL, DINNER);
}

// round 8
// speedup vs baseline: 1.3104x; 1.0406x over previous
#include <cuda_runtime.h>
#include <cuda_fp16.h>
#include <math.h>
#include <stdint.h>

#define TOKENS 4096
#define DMODEL 1024
#define DINNER 2048
#define DSTATE 16
#define SEQL   2048

// Scratch (static device globals — no runtime allocation allowed)
__device__ __align__(256) float  g_xz [TOKENS * 2 * DINNER];  // GEMM1 out: xi-preconv | z
__device__ __align__(256) float  g_xi [TOKENS * DINNER];      // conv+silu output (fp32)
__device__ __align__(256) float  g_dbc[TOKENS * 33];
__device__ __align__(256) float  g_dbcp[8][TOKENS * 33];
__device__ __align__(256) __half g_xh [TOKENS * DMODEL];      // half x
__device__ __align__(256) __half g_wh [2 * DINNER * DMODEL];  // half W_in
__device__ __align__(256) __half g_woh[DMODEL * DINNER];      // half W_out
__device__ __align__(256) __half g_yh [TOKENS * DINNER];      // half scan output

// ---------------------------------------------------------------------------
__device__ __forceinline__ void cp_async16(void* smem_dst, const void* gmem_src) {
    uint32_t s = (uint32_t)__cvta_generic_to_shared(smem_dst);
    asm volatile("cp.async.cg.shared.global [%0], [%1], 16;" :: "r"(s), "l"(gmem_src));
}

__device__ __forceinline__ void mma_f16(float* c, const uint32_t* a, const uint32_t* b) {
    asm volatile(
        "mma.sync.aligned.m16n8k16.row.col.f32.f16.f16.f32 "
        "{%0,%1,%2,%3}, {%4,%5,%6,%7}, {%8,%9}, {%0,%1,%2,%3};"
        : "+f"(c[0]), "+f"(c[1]), "+f"(c[2]), "+f"(c[3])
        : "r"(a[0]), "r"(a[1]), "r"(a[2]), "r"(a[3]), "r"(b[0]), "r"(b[1]));
}

__device__ __forceinline__ void ldsm_x4(uint32_t& r0, uint32_t& r1, uint32_t& r2,
                                        uint32_t& r3, uint32_t saddr) {
    asm volatile("ldmatrix.sync.aligned.m8n8.x4.shared.b16 {%0,%1,%2,%3}, [%4];"
        : "=r"(r0), "=r"(r1), "=r"(r2), "=r"(r3) : "r"(saddr));
}

// ---------------------------------------------------------------------------
// FP16 mma.sync GEMM with ldmatrix: C[M,N] = A[M,K]h * B[N,K]h^T, fp32 accum.
// BM=128, BN=128, BK=64. 8 warps (2 x 4), warp tile 64x32. 3-stage cp.async.
// __launch_bounds__(256, 2): ~120 regs -> 2 CTAs/SM (smem 110.6KB x 2 = 221KB).
// ---------------------------------------------------------------------------
#define BM 128
#define BN 128
#define BK 64
#define STRH 72                              // halfs per smem row
#define A_HALFS (BM * STRH)
#define B_HALFS (BN * STRH)
#define STG_HALFS (A_HALFS + B_HALFS)
#define GEMM_SMEM (3 * STG_HALFS * 2)        // 110592 B

__global__ void __launch_bounds__(256, 2)
h_gemm_nt(const __half* __restrict__ A, const __half* __restrict__ B,
          float* __restrict__ C, int M, int N, int K) {
    extern __shared__ __half sh[];
    constexpr int WN = 32;                   // warp-tile N
    constexpr int NFN = 4;                   // b frags per warp
    constexpr int NPAIR = 2;

    const int tid  = threadIdx.x;
    const int wid  = tid >> 5;
    const int lane = tid & 31;
    const int gid  = lane >> 2;              // 0..7
    const int t4   = lane & 3;               // 0..3
    const int wm   = wid & 1;                // 64 rows each
    const int wn   = wid >> 1;               // 32 cols each
    const int row0 = blockIdx.y * BM;
    const int col0 = blockIdx.x * BN;

    const uint32_t sbase = (uint32_t)__cvta_generic_to_shared(sh);

    // ldmatrix lane->row mappings
    const int a_row  = wm * 64 + (lane & 15);        // + fm*16
    const int a_colh = (lane >> 4) * 8;              // k-half select
    const int b_row  = (lane & 7) + ((lane >> 4) * 8);
    const int b_colh = ((lane >> 3) & 1) * 8;

    // loader: 16B granules
    const int lrow = tid >> 3;               // 0..31
    const int lchk = (tid & 7) * 8;          // half offset 0..56

    float acc[4][NFN][4] = {};
    const int niter = K / BK;

    auto load_stage = [&](int stage, int k0) {
        __half* Sa = sh + stage * STG_HALFS;
        __half* Sb = Sa + A_HALFS;
#pragma unroll
        for (int i = 0; i < BM / 32; i++) {
            int r = lrow + i * 32;
            cp_async16(&Sa[r * STRH + lchk], A + (size_t)(row0 + r) * K + k0 + lchk);
        }
#pragma unroll
        for (int i = 0; i < BN / 32; i++) {
            int r = lrow + i * 32;
            cp_async16(&Sb[r * STRH + lchk], B + (size_t)(col0 + r) * K + k0 + lchk);
        }
    };

    load_stage(0, 0);
    asm volatile("cp.async.commit_group;");
    if (niter > 1) load_stage(1, BK);
    asm volatile("cp.async.commit_group;");

    int s = 0;
    for (int it = 0; it < niter; it++) {
        asm volatile("cp.async.wait_group 1;");
        __syncthreads();

        if (it + 2 < niter) load_stage((it + 2) % 3, (it + 2) * BK);
        asm volatile("cp.async.commit_group;");

        const uint32_t sA = sbase + (uint32_t)(s * STG_HALFS) * 2;
        const uint32_t sB = sA + A_HALFS * 2;
#pragma unroll
        for (int kk = 0; kk < BK / 16; kk++) {
            const int kb = kk * 16;
            uint32_t af[4][4], bf[NFN][2];
#pragma unroll
            for (int fm = 0; fm < 4; fm++)
                ldsm_x4(af[fm][0], af[fm][1], af[fm][2], af[fm][3],
                        sA + (uint32_t)((a_row + fm * 16) * STRH + kb + a_colh) * 2);
#pragma unroll
            for (int p = 0; p < NPAIR; p++)
                ldsm_x4(bf[2 * p][0], bf[2 * p][1], bf[2 * p + 1][0], bf[2 * p + 1][1],
                        sB + (uint32_t)((wn * WN + p * 16 + b_row) * STRH + kb + b_colh) * 2);
#pragma unroll
            for (int fm = 0; fm < 4; fm++)
#pragma unroll
                for (int fn = 0; fn < NFN; fn++)
                    mma_f16(acc[fm][fn], af[fm], bf[fn]);
        }
        __syncthreads();
        s = (s + 1) % 3;
    }

#pragma unroll
    for (int fm = 0; fm < 4; fm++) {
        int r = row0 + wm * 64 + fm * 16 + gid;
#pragma unroll
        for (int fn = 0; fn < NFN; fn++) {
            int cbase = col0 + wn * WN + fn * 8 + t4 * 2;
            float2* p0 = (float2*)&C[(size_t)r * N + cbase];
            float2* p1 = (float2*)&C[(size_t)(r + 8) * N + cbase];
            *p0 = make_float2(acc[fm][fn][0], acc[fm][fn][1]);
            *p1 = make_float2(acc[fm][fn][2], acc[fm][fn][3]);
        }
    }
}

// ---------------------------------------------------------------------------
// fp32 -> fp16 conversion (GEMM operand prep), 8 elems/thread
// ---------------------------------------------------------------------------
__global__ void cvt_h(const float* __restrict__ in, __half* __restrict__ out, int n8) {
    int i = blockIdx.x * blockDim.x + threadIdx.x;
    if (i >= n8) return;
    float4 v0 = ((const float4*)in)[2 * i];
    float4 v1 = ((const float4*)in)[2 * i + 1];
    __half2 h[4];
    h[0] = __float22half2_rn(make_float2(v0.x, v0.y));
    h[1] = __float22half2_rn(make_float2(v0.z, v0.w));
    h[2] = __float22half2_rn(make_float2(v1.x, v1.y));
    h[3] = __float22half2_rn(make_float2(v1.z, v1.w));
    ((uint4*)out)[i] = *(uint4*)h;
}

// ---------------------------------------------------------------------------
// Causal depthwise conv (width 4) + bias + SiLU on first half of xz -> g_xi
// ---------------------------------------------------------------------------
__global__ void conv_silu_k(const float* __restrict__ cw, const float* __restrict__ cb) {
    int idx = blockIdx.x * blockDim.x + threadIdx.x;
    int d = idx & (DINNER - 1);
    int t = idx >> 11;
    int l = t & (SEQL - 1);
    float w0 = cw[d * 4 + 0], w1 = cw[d * 4 + 1], w2 = cw[d * 4 + 2], w3 = cw[d * 4 + 3];
    float acc = cb[d];
    size_t base = (size_t)t * (2 * DINNER) + d;
    if (l >= 3) acc += g_xz[base - 3 * (size_t)(2 * DINNER)] * w0;
    if (l >= 2) acc += g_xz[base - 2 * (size_t)(2 * DINNER)] * w1;
    if (l >= 1) acc += g_xz[base - 1 * (size_t)(2 * DINNER)] * w2;
    acc += g_xz[base] * w3;
    g_xi[idx] = acc / (1.f + __expf(-acc));
}

// ---------------------------------------------------------------------------
// x_dbl split-K partials + deterministic reduce (fp32)
// ---------------------------------------------------------------------------
__global__ void xdbl_part_k(const float* __restrict__ Wx) {
    __shared__ float Xs[64][33];
    __shared__ float Ws[33][33];
    const int tx = threadIdx.x, ty = threadIdx.y;   // (33,8)
    const int tid = ty * 33 + tx;
    const int tok0 = blockIdx.x * 64;
    const int kbase = blockIdx.y * 256;
    float acc[8] = {};
    for (int k0 = kbase; k0 < kbase + 256; k0 += 32) {
        for (int i = tid; i < 64 * 32; i += 264) {
            int tt = i >> 5, kk = i & 31;
            Xs[tt][kk] = g_xi[(size_t)(tok0 + tt) * DINNER + k0 + kk];
        }
        for (int i = tid; i < 33 * 32; i += 264) {
            int e = i >> 5, kk = i & 31;
            Ws[e][kk] = Wx[(size_t)e * DINNER + k0 + kk];
        }
        __syncthreads();
#pragma unroll
        for (int kk = 0; kk < 32; kk++) {
            float w = Ws[tx][kk];
#pragma unroll
            for (int i = 0; i < 8; i++)
                acc[i] += Xs[ty * 8 + i][kk] * w;
        }
        __syncthreads();
    }
#pragma unroll
    for (int i = 0; i < 8; i++)
        g_dbcp[blockIdx.y][(size_t)(tok0 + ty * 8 + i) * 33 + tx] = acc[i];
}

__global__ void xdbl_reduce_k() {
    int i = blockIdx.x * blockDim.x + threadIdx.x;
    if (i >= TOKENS * 33) return;
    float s = 0.f;
#pragma unroll
    for (int p = 0; p < 8; p++) s += g_dbcp[p][i];
    g_dbc[i] = s;
}

// ---------------------------------------------------------------------------
// Selective scan: 8 channels/block (128 thr), grid (256, 2) = 512 blocks.
// ---------------------------------------------------------------------------
#define CH 32
#define CPB 8
#define PSTRIDE 17

__global__ void __launch_bounds__(128)
scan_k(const float* __restrict__ A_log, const float* __restrict__ Dvec,
       const float* __restrict__ Wdt, const float* __restrict__ bdt) {
    __shared__ float sB[CH][16], sC[CH][16];
    __shared__ float sX[CH][CPB], sZ[CH][CPB], sDT[CH][CPB];
    __shared__ float sP[CH][CPB * PSTRIDE];
    const int tid = threadIdx.x;              // 128
    const int dd = tid >> 4, n = tid & 15;    // channel 0..7, state 0..15
    const int q8 = tid & 7;                   // channel index for IO phases
    const int b = blockIdx.y;
    const int d0 = blockIdx.x * CPB;

    const float a  = -__expf(A_log[(d0 + dd) * DSTATE + n]);
    const float wq = Wdt[d0 + q8];
    const float bq = bdt[d0 + q8];
    const float Dq = Dvec[d0 + q8];
    float h = 0.f;

    for (int c = 0; c < SEQL / CH; c++) {
        const int tok0 = b * SEQL + c * CH;
        for (int i = tid; i < CH * 33; i += 128) {
            int tt = i / 33, e = i - tt * 33;
            float v = g_dbc[(size_t)(tok0 + tt) * 33 + e];
            if (e >= 17)     sC[tt][e - 17] = v;
            else if (e >= 1) sB[tt][e - 1]  = v;
        }
        for (int i = tid; i < CH * CPB; i += 128) {
            int tt = i >> 3;
            sX[tt][q8] = g_xi[(size_t)(tok0 + tt) * DINNER + d0 + q8];
            sZ[tt][q8] = g_xz[(size_t)(tok0 + tt) * (2 * DINNER) + DINNER + d0 + q8];
            float u = g_dbc[(size_t)(tok0 + tt) * 33] * wq + bq;
            sDT[tt][q8] = (u > 20.f) ? u : log1pf(__expf(u));
        }
        __syncthreads();
#pragma unroll
        for (int t = 0; t < CH; t++) {
            float dtv = sDT[t][dd];
            float xv  = sX[t][dd];
            float dA  = __expf(dtv * a);
            h = dA * h + (dtv * sB[t][n]) * xv;
            sP[t][dd * PSTRIDE + n] = h * sC[t][n];
        }
        __syncthreads();
        for (int i = tid; i < CH * CPB; i += 128) {
            int tt = i >> 3;
            float s = 0.f;
#pragma unroll
            for (int j = 0; j < 16; j++) s += sP[tt][q8 * PSTRIDE + j];
            float xv = sX[tt][q8], zv = sZ[tt][q8];
            float yv = (s + Dq * xv) * (zv / (1.f + __expf(-zv)));
            g_yh[(size_t)(tok0 + tt) * DINNER + d0 + q8] = __float2half_rn(yv);
        }
        __syncthreads();
    }
}

// ---------------------------------------------------------------------------
extern "C" void kernel_launch(void* const* d_in, const int* in_sizes, int n_in,
                              void* d_out, int out_size) {
    const float* x     = (const float*)d_in[0];
    const float* W_in  = (const float*)d_in[1];
    const float* convw = (const float*)d_in[2];
    const float* convb = (const float*)d_in[3];
    const float* W_x   = (const float*)d_in[4];
    const float* W_dt  = (const float*)d_in[5];
    const float* b_dt  = (const float*)d_in[6];
    const float* A_log = (const float*)d_in[7];
    const float* Dv    = (const float*)d_in[8];
    const float* W_out = (const float*)d_in[9];
    float* out = (float*)d_out;

    float *xz;
    __half *xh, *wh, *woh, *yh;
    cudaGetSymbolAddress((void**)&xz,  g_xz);
    cudaGetSymbolAddress((void**)&xh,  g_xh);
    cudaGetSymbolAddress((void**)&wh,  g_wh);
    cudaGetSymbolAddress((void**)&woh, g_woh);
    cudaGetSymbolAddress((void**)&yh,  g_yh);

    cudaFuncSetAttribute(h_gemm_nt, cudaFuncAttributeMaxDynamicSharedMemorySize, GEMM_SMEM);

    // 0) convert GEMM operands to fp16
    cvt_h<<<(TOKENS * DMODEL / 8 + 255) / 256, 256>>>(x, xh, TOKENS * DMODEL / 8);
    cvt_h<<<(2 * DINNER * DMODEL / 8 + 255) / 256, 256>>>(W_in, wh, 2 * DINNER * DMODEL / 8);
    cvt_h<<<(DMODEL * DINNER / 8 + 255) / 256, 256>>>(W_out, woh, DMODEL * DINNER / 8);

    // 1) xz = x @ W_in^T   [4096 x 4096], K=1024
    h_gemm_nt<<<dim3(4096 / BN, TOKENS / BM), 256, GEMM_SMEM>>>(xh, wh, xz, TOKENS, 4096, DMODEL);

    // 2) causal depthwise conv + silu -> g_xi
    conv_silu_k<<<(TOKENS * DINNER) / 256, 256>>>(convw, convb);

    // 3) x_dbl = xi @ W_x^T (split-K + deterministic reduce)
    xdbl_part_k<<<dim3(TOKENS / 64, 8), dim3(33, 8)>>>(W_x);
    xdbl_reduce_k<<<(TOKENS * 33 + 255) / 256, 256>>>();

    // 4) selective scan -> g_yh (half)
    scan_k<<<dim3(DINNER / CPB, 2), 128>>>(A_log, Dv, W_dt, b_dt);

    // 5) out = y @ W_out^T   [4096 x 1024], K=2048
    h_gemm_nt<<<dim3(DMODEL / BN, TOKENS / BM), 256, GEMM_SMEM>>>(yh, woh, out, TOKENS, DMODEL, DINNER);
}

// round 9
// speedup vs baseline: 1.3661x; 1.0425x over previous
#include <cuda_runtime.h>
#include <cuda_fp16.h>
#include <math.h>
#include <stdint.h>

#define TOKENS 4096
#define DMODEL 1024
#define DINNER 2048
#define DSTATE 16
#define SEQL   2048

// Scratch (static device globals — no runtime allocation allowed)
__device__ __align__(256) float  g_xz [TOKENS * 2 * DINNER];  // GEMM1 out: xi-preconv | z
__device__ __align__(256) float  g_xi [TOKENS * DINNER];      // conv+silu output (fp32)
__device__ __align__(256) float  g_dbc[TOKENS * 33];
__device__ __align__(256) float  g_dbcp[8][TOKENS * 33];
__device__ __align__(256) __half g_xh [TOKENS * DMODEL];      // half x
__device__ __align__(256) __half g_wh [2 * DINNER * DMODEL];  // half W_in
__device__ __align__(256) __half g_woh[DMODEL * DINNER];      // half W_out
__device__ __align__(256) __half g_yh [TOKENS * DINNER];      // half scan output

// ---------------------------------------------------------------------------
__device__ __forceinline__ void cp_async16(void* smem_dst, const void* gmem_src) {
    uint32_t s = (uint32_t)__cvta_generic_to_shared(smem_dst);
    asm volatile("cp.async.cg.shared.global [%0], [%1], 16;" :: "r"(s), "l"(gmem_src));
}

__device__ __forceinline__ void mma_f16(float* c, const uint32_t* a, const uint32_t* b) {
    asm volatile(
        "mma.sync.aligned.m16n8k16.row.col.f32.f16.f16.f32 "
        "{%0,%1,%2,%3}, {%4,%5,%6,%7}, {%8,%9}, {%0,%1,%2,%3};"
        : "+f"(c[0]), "+f"(c[1]), "+f"(c[2]), "+f"(c[3])
        : "r"(a[0]), "r"(a[1]), "r"(a[2]), "r"(a[3]), "r"(b[0]), "r"(b[1]));
}

__device__ __forceinline__ void ldsm_x4(uint32_t& r0, uint32_t& r1, uint32_t& r2,
                                        uint32_t& r3, uint32_t saddr) {
    asm volatile("ldmatrix.sync.aligned.m8n8.x4.shared.b16 {%0,%1,%2,%3}, [%4];"
        : "=r"(r0), "=r"(r1), "=r"(r2), "=r"(r3) : "r"(saddr));
}

// ---------------------------------------------------------------------------
// FP16 mma.sync GEMM with ldmatrix (unchanged from R8): BM=BN=128, BK=64,
// 8 warps, 3-stage cp.async, 2 CTAs/SM.
// ---------------------------------------------------------------------------
#define BM 128
#define BN 128
#define BK 64
#define STRH 72
#define A_HALFS (BM * STRH)
#define B_HALFS (BN * STRH)
#define STG_HALFS (A_HALFS + B_HALFS)
#define GEMM_SMEM (3 * STG_HALFS * 2)        // 110592 B

__global__ void __launch_bounds__(256, 2)
h_gemm_nt(const __half* __restrict__ A, const __half* __restrict__ B,
          float* __restrict__ C, int M, int N, int K) {
    extern __shared__ __half sh[];
    constexpr int WN = 32;
    constexpr int NFN = 4;
    constexpr int NPAIR = 2;

    const int tid  = threadIdx.x;
    const int wid  = tid >> 5;
    const int lane = tid & 31;
    const int gid  = lane >> 2;
    const int t4   = lane & 3;
    const int wm   = wid & 1;
    const int wn   = wid >> 1;
    const int row0 = blockIdx.y * BM;
    const int col0 = blockIdx.x * BN;

    const uint32_t sbase = (uint32_t)__cvta_generic_to_shared(sh);

    const int a_row  = wm * 64 + (lane & 15);
    const int a_colh = (lane >> 4) * 8;
    const int b_row  = (lane & 7) + ((lane >> 4) * 8);
    const int b_colh = ((lane >> 3) & 1) * 8;

    const int lrow = tid >> 3;
    const int lchk = (tid & 7) * 8;

    float acc[4][NFN][4] = {};
    const int niter = K / BK;

    auto load_stage = [&](int stage, int k0) {
        __half* Sa = sh + stage * STG_HALFS;
        __half* Sb = Sa + A_HALFS;
#pragma unroll
        for (int i = 0; i < BM / 32; i++) {
            int r = lrow + i * 32;
            cp_async16(&Sa[r * STRH + lchk], A + (size_t)(row0 + r) * K + k0 + lchk);
        }
#pragma unroll
        for (int i = 0; i < BN / 32; i++) {
            int r = lrow + i * 32;
            cp_async16(&Sb[r * STRH + lchk], B + (size_t)(col0 + r) * K + k0 + lchk);
        }
    };

    load_stage(0, 0);
    asm volatile("cp.async.commit_group;");
    if (niter > 1) load_stage(1, BK);
    asm volatile("cp.async.commit_group;");

    int s = 0;
    for (int it = 0; it < niter; it++) {
        asm volatile("cp.async.wait_group 1;");
        __syncthreads();

        if (it + 2 < niter) load_stage((it + 2) % 3, (it + 2) * BK);
        asm volatile("cp.async.commit_group;");

        const uint32_t sA = sbase + (uint32_t)(s * STG_HALFS) * 2;
        const uint32_t sB = sA + A_HALFS * 2;
#pragma unroll
        for (int kk = 0; kk < BK / 16; kk++) {
            const int kb = kk * 16;
            uint32_t af[4][4], bf[NFN][2];
#pragma unroll
            for (int fm = 0; fm < 4; fm++)
                ldsm_x4(af[fm][0], af[fm][1], af[fm][2], af[fm][3],
                        sA + (uint32_t)((a_row + fm * 16) * STRH + kb + a_colh) * 2);
#pragma unroll
            for (int p = 0; p < NPAIR; p++)
                ldsm_x4(bf[2 * p][0], bf[2 * p][1], bf[2 * p + 1][0], bf[2 * p + 1][1],
                        sB + (uint32_t)((wn * WN + p * 16 + b_row) * STRH + kb + b_colh) * 2);
#pragma unroll
            for (int fm = 0; fm < 4; fm++)
#pragma unroll
                for (int fn = 0; fn < NFN; fn++)
                    mma_f16(acc[fm][fn], af[fm], bf[fn]);
        }
        __syncthreads();
        s = (s + 1) % 3;
    }

#pragma unroll
    for (int fm = 0; fm < 4; fm++) {
        int r = row0 + wm * 64 + fm * 16 + gid;
#pragma unroll
        for (int fn = 0; fn < NFN; fn++) {
            int cbase = col0 + wn * WN + fn * 8 + t4 * 2;
            float2* p0 = (float2*)&C[(size_t)r * N + cbase];
            float2* p1 = (float2*)&C[(size_t)(r + 8) * N + cbase];
            *p0 = make_float2(acc[fm][fn][0], acc[fm][fn][1]);
            *p1 = make_float2(acc[fm][fn][2], acc[fm][fn][3]);
        }
    }
}

// ---------------------------------------------------------------------------
// Fused fp32->fp16 conversion of x, W_in, W_out (one launch)
// ---------------------------------------------------------------------------
#define N4_X  (TOKENS * DMODEL / 4)              // 1048576... /4 floats
#define N4_WI (2 * DINNER * DMODEL / 4)
#define N4_WO (DMODEL * DINNER / 4)

__global__ void cvt_all_k(const float* __restrict__ x, const float* __restrict__ Wi,
                          const float* __restrict__ Wo) {
    int i = blockIdx.x * blockDim.x + threadIdx.x;   // float4 index
    const float* src; __half* dst; int off;
    if (i < N4_X)                  { src = x;  dst = g_xh;  off = i; }
    else if (i < N4_X + N4_WI)     { src = Wi; dst = g_wh;  off = i - N4_X; }
    else if (i < N4_X + N4_WI + N4_WO) { src = Wo; dst = g_woh; off = i - N4_X - N4_WI; }
    else return;
    float4 v = ((const float4*)src)[off];
    __half2 h0 = __float22half2_rn(make_float2(v.x, v.y));
    __half2 h1 = __float22half2_rn(make_float2(v.z, v.w));
    ((uint2*)dst)[off] = make_uint2(*(uint32_t*)&h0, *(uint32_t*)&h1);
}

// ---------------------------------------------------------------------------
// Causal depthwise conv (width 4) + bias + SiLU on first half of xz -> g_xi
// ---------------------------------------------------------------------------
__global__ void conv_silu_k(const float* __restrict__ cw, const float* __restrict__ cb) {
    int idx = blockIdx.x * blockDim.x + threadIdx.x;
    int d = idx & (DINNER - 1);
    int t = idx >> 11;
    int l = t & (SEQL - 1);
    float w0 = cw[d * 4 + 0], w1 = cw[d * 4 + 1], w2 = cw[d * 4 + 2], w3 = cw[d * 4 + 3];
    float acc = cb[d];
    size_t base = (size_t)t * (2 * DINNER) + d;
    if (l >= 3) acc += g_xz[base - 3 * (size_t)(2 * DINNER)] * w0;
    if (l >= 2) acc += g_xz[base - 2 * (size_t)(2 * DINNER)] * w1;
    if (l >= 1) acc += g_xz[base - 1 * (size_t)(2 * DINNER)] * w2;
    acc += g_xz[base] * w3;
    g_xi[idx] = acc / (1.f + __expf(-acc));
}

// ---------------------------------------------------------------------------
// x_dbl split-K partials + deterministic reduce (fp32)
// ---------------------------------------------------------------------------
__global__ void xdbl_part_k(const float* __restrict__ Wx) {
    __shared__ float Xs[64][33];
    __shared__ float Ws[33][33];
    const int tx = threadIdx.x, ty = threadIdx.y;   // (33,8)
    const int tid = ty * 33 + tx;
    const int tok0 = blockIdx.x * 64;
    const int kbase = blockIdx.y * 256;
    float acc[8] = {};
    for (int k0 = kbase; k0 < kbase + 256; k0 += 32) {
        for (int i = tid; i < 64 * 32; i += 264) {
            int tt = i >> 5, kk = i & 31;
            Xs[tt][kk] = g_xi[(size_t)(tok0 + tt) * DINNER + k0 + kk];
        }
        for (int i = tid; i < 33 * 32; i += 264) {
            int e = i >> 5, kk = i & 31;
            Ws[e][kk] = Wx[(size_t)e * DINNER + k0 + kk];
        }
        __syncthreads();
#pragma unroll
        for (int kk = 0; kk < 32; kk++) {
            float w = Ws[tx][kk];
#pragma unroll
            for (int i = 0; i < 8; i++)
                acc[i] += Xs[ty * 8 + i][kk] * w;
        }
        __syncthreads();
    }
#pragma unroll
    for (int i = 0; i < 8; i++)
        g_dbcp[blockIdx.y][(size_t)(tok0 + ty * 8 + i) * 33 + tx] = acc[i];
}

__global__ void xdbl_reduce_k() {
    int i = blockIdx.x * blockDim.x + threadIdx.x;
    if (i >= TOKENS * 33) return;
    float s = 0.f;
#pragma unroll
    for (int p = 0; p < 8; p++) s += g_dbcp[p][i];
    g_dbc[i] = s;
}

// ---------------------------------------------------------------------------
// Selective scan, latency-chain-split version.
// Per chunk: Loop A precomputes dA[t], bx[t] into registers (all independent
// -> MUFU/LDS pipeline at throughput); Loop B is the pure 4-cyc FFMA chain
// with off-chain C-multiply + STS. Same arithmetic/order as R8 (bit-identical).
// ---------------------------------------------------------------------------
#define CH 32
#define CPB 8
#define PSTRIDE 17

__global__ void __launch_bounds__(128, 4)
scan_k(const float* __restrict__ A_log, const float* __restrict__ Dvec,
       const float* __restrict__ Wdt, const float* __restrict__ bdt) {
    __shared__ float sB[CH][16], sC[CH][16];
    __shared__ float sX[CH][CPB], sZ[CH][CPB], sDT[CH][CPB];
    __shared__ float sP[CH][CPB * PSTRIDE];
    const int tid = threadIdx.x;              // 128
    const int dd = tid >> 4, n = tid & 15;    // channel 0..7, state 0..15
    const int q8 = tid & 7;                   // channel index for IO phases
    const int b = blockIdx.y;
    const int d0 = blockIdx.x * CPB;

    const float a  = -__expf(A_log[(d0 + dd) * DSTATE + n]);
    const float wq = Wdt[d0 + q8];
    const float bq = bdt[d0 + q8];
    const float Dq = Dvec[d0 + q8];
    float h = 0.f;

    for (int c = 0; c < SEQL / CH; c++) {
        const int tok0 = b * SEQL + c * CH;
        for (int i = tid; i < CH * 33; i += 128) {
            int tt = i / 33, e = i - tt * 33;
            float v = g_dbc[(size_t)(tok0 + tt) * 33 + e];
            if (e >= 17)     sC[tt][e - 17] = v;
            else if (e >= 1) sB[tt][e - 1]  = v;
        }
        for (int i = tid; i < CH * CPB; i += 128) {
            int tt = i >> 3;
            sX[tt][q8] = g_xi[(size_t)(tok0 + tt) * DINNER + d0 + q8];
            sZ[tt][q8] = g_xz[(size_t)(tok0 + tt) * (2 * DINNER) + DINNER + d0 + q8];
            float u = g_dbc[(size_t)(tok0 + tt) * 33] * wq + bq;
            sDT[tt][q8] = (u > 20.f) ? u : log1pf(__expf(u));
        }
        __syncthreads();

        // Loop A: independent per-step precompute (pipelines at throughput)
        float dA[CH], bx[CH];
#pragma unroll
        for (int t = 0; t < CH; t++) {
            float dtv = sDT[t][dd];
            dA[t] = __expf(dtv * a);
            bx[t] = (dtv * sB[t][n]) * sX[t][dd];
        }
        // Loop B: pure FFMA recurrence; C-multiply + STS trail off-chain
#pragma unroll
        for (int t = 0; t < CH; t++) {
            h = fmaf(dA[t], h, bx[t]);
            sP[t][dd * PSTRIDE + n] = h * sC[t][n];
        }
        __syncthreads();

        for (int i = tid; i < CH * CPB; i += 128) {
            int tt = i >> 3;
            float s = 0.f;
#pragma unroll
            for (int j = 0; j < 16; j++) s += sP[tt][q8 * PSTRIDE + j];
            float xv = sX[tt][q8], zv = sZ[tt][q8];
            float yv = (s + Dq * xv) * (zv / (1.f + __expf(-zv)));
            g_yh[(size_t)(tok0 + tt) * DINNER + d0 + q8] = __float2half_rn(yv);
        }
        __syncthreads();
    }
}

// ---------------------------------------------------------------------------
extern "C" void kernel_launch(void* const* d_in, const int* in_sizes, int n_in,
                              void* d_out, int out_size) {
    const float* x     = (const float*)d_in[0];
    const float* W_in  = (const float*)d_in[1];
    const float* convw = (const float*)d_in[2];
    const float* convb = (const float*)d_in[3];
    const float* W_x   = (const float*)d_in[4];
    const float* W_dt  = (const float*)d_in[5];
    const float* b_dt  = (const float*)d_in[6];
    const float* A_log = (const float*)d_in[7];
    const float* Dv    = (const float*)d_in[8];
    const float* W_out = (const float*)d_in[9];
    float* out = (float*)d_out;

    float *xz;
    __half *xh, *wh, *woh, *yh;
    cudaGetSymbolAddress((void**)&xz,  g_xz);
    cudaGetSymbolAddress((void**)&xh,  g_xh);
    cudaGetSymbolAddress((void**)&wh,  g_wh);
    cudaGetSymbolAddress((void**)&woh, g_woh);
    cudaGetSymbolAddress((void**)&yh,  g_yh);

    cudaFuncSetAttribute(h_gemm_nt, cudaFuncAttributeMaxDynamicSharedMemorySize, GEMM_SMEM);

    // 0) convert all GEMM operands to fp16 (single launch)
    const int n4tot = N4_X + N4_WI + N4_WO;
    cvt_all_k<<<(n4tot + 255) / 256, 256>>>(x, W_in, W_out);

    // 1) xz = x @ W_in^T   [4096 x 4096], K=1024
    h_gemm_nt<<<dim3(4096 / BN, TOKENS / BM), 256, GEMM_SMEM>>>(xh, wh, xz, TOKENS, 4096, DMODEL);

    // 2) causal depthwise conv + silu -> g_xi
    conv_silu_k<<<(TOKENS * DINNER) / 256, 256>>>(convw, convb);

    // 3) x_dbl = xi @ W_x^T (split-K + deterministic reduce)  [profiled slot]
    xdbl_part_k<<<dim3(TOKENS / 64, 8), dim3(33, 8)>>>(W_x);
    xdbl_reduce_k<<<(TOKENS * 33 + 255) / 256, 256>>>();

    // 4) selective scan -> g_yh (half)
    scan_k<<<dim3(DINNER / CPB, 2), 128>>>(A_log, Dv, W_dt, b_dt);

    // 5) out = y @ W_out^T   [4096 x 1024], K=2048
    h_gemm_nt<<<dim3(DMODEL / BN, TOKENS / BM), 256, GEMM_SMEM>>>(yh, woh, out, TOKENS, DMODEL, DINNER);
}

// round 10
// speedup vs baseline: 1.6086x; 1.1776x over previous
#include <cuda_runtime.h>
#include <cuda_fp16.h>
#include <math.h>
#include <stdint.h>

#define TOKENS 4096
#define DMODEL 1024
#define DINNER 2048
#define DSTATE 16
#define SEQL   2048

// Scratch (static device globals — no runtime allocation allowed)
__device__ __align__(256) float  g_xz [TOKENS * 2 * DINNER];  // GEMM1 out: xi-preconv | z
__device__ __align__(256) float  g_xi [TOKENS * DINNER];      // conv+silu output (fp32)
__device__ __align__(256) float  g_dbc[TOKENS * 33];
__device__ __align__(256) float  g_dbcp[8][TOKENS * 33];
__device__ __align__(256) __half g_xh [TOKENS * DMODEL];      // half x
__device__ __align__(256) __half g_wh [2 * DINNER * DMODEL];  // half W_in
__device__ __align__(256) __half g_woh[DMODEL * DINNER];      // half W_out
__device__ __align__(256) __half g_yh [TOKENS * DINNER];      // half scan output

// ---------------------------------------------------------------------------
__device__ __forceinline__ void cp_async16(void* smem_dst, const void* gmem_src) {
    uint32_t s = (uint32_t)__cvta_generic_to_shared(smem_dst);
    asm volatile("cp.async.cg.shared.global [%0], [%1], 16;" :: "r"(s), "l"(gmem_src));
}

__device__ __forceinline__ void mma_f16(float* c, const uint32_t* a, const uint32_t* b) {
    asm volatile(
        "mma.sync.aligned.m16n8k16.row.col.f32.f16.f16.f32 "
        "{%0,%1,%2,%3}, {%4,%5,%6,%7}, {%8,%9}, {%0,%1,%2,%3};"
        : "+f"(c[0]), "+f"(c[1]), "+f"(c[2]), "+f"(c[3])
        : "r"(a[0]), "r"(a[1]), "r"(a[2]), "r"(a[3]), "r"(b[0]), "r"(b[1]));
}

__device__ __forceinline__ void ldsm_x4(uint32_t& r0, uint32_t& r1, uint32_t& r2,
                                        uint32_t& r3, uint32_t saddr) {
    asm volatile("ldmatrix.sync.aligned.m8n8.x4.shared.b16 {%0,%1,%2,%3}, [%4];"
        : "=r"(r0), "=r"(r1), "=r"(r2), "=r"(r3) : "r"(saddr));
}

// ---------------------------------------------------------------------------
// FP16 mma.sync GEMM with ldmatrix (unchanged from R8): BM=BN=128, BK=64,
// 8 warps, 3-stage cp.async, 2 CTAs/SM.
// ---------------------------------------------------------------------------
#define BM 128
#define BN 128
#define BK 64
#define STRH 72
#define A_HALFS (BM * STRH)
#define B_HALFS (BN * STRH)
#define STG_HALFS (A_HALFS + B_HALFS)
#define GEMM_SMEM (3 * STG_HALFS * 2)        // 110592 B

__global__ void __launch_bounds__(256, 2)
h_gemm_nt(const __half* __restrict__ A, const __half* __restrict__ B,
          float* __restrict__ C, int M, int N, int K) {
    extern __shared__ __half sh[];
    constexpr int WN = 32;
    constexpr int NFN = 4;
    constexpr int NPAIR = 2;

    const int tid  = threadIdx.x;
    const int wid  = tid >> 5;
    const int lane = tid & 31;
    const int gid  = lane >> 2;
    const int t4   = lane & 3;
    const int wm   = wid & 1;
    const int wn   = wid >> 1;
    const int row0 = blockIdx.y * BM;
    const int col0 = blockIdx.x * BN;

    const uint32_t sbase = (uint32_t)__cvta_generic_to_shared(sh);

    const int a_row  = wm * 64 + (lane & 15);
    const int a_colh = (lane >> 4) * 8;
    const int b_row  = (lane & 7) + ((lane >> 4) * 8);
    const int b_colh = ((lane >> 3) & 1) * 8;

    const int lrow = tid >> 3;
    const int lchk = (tid & 7) * 8;

    float acc[4][NFN][4] = {};
    const int niter = K / BK;

    auto load_stage = [&](int stage, int k0) {
        __half* Sa = sh + stage * STG_HALFS;
        __half* Sb = Sa + A_HALFS;
#pragma unroll
        for (int i = 0; i < BM / 32; i++) {
            int r = lrow + i * 32;
            cp_async16(&Sa[r * STRH + lchk], A + (size_t)(row0 + r) * K + k0 + lchk);
        }
#pragma unroll
        for (int i = 0; i < BN / 32; i++) {
            int r = lrow + i * 32;
            cp_async16(&Sb[r * STRH + lchk], B + (size_t)(col0 + r) * K + k0 + lchk);
        }
    };

    load_stage(0, 0);
    asm volatile("cp.async.commit_group;");
    if (niter > 1) load_stage(1, BK);
    asm volatile("cp.async.commit_group;");

    int s = 0;
    for (int it = 0; it < niter; it++) {
        asm volatile("cp.async.wait_group 1;");
        __syncthreads();

        if (it + 2 < niter) load_stage((it + 2) % 3, (it + 2) * BK);
        asm volatile("cp.async.commit_group;");

        const uint32_t sA = sbase + (uint32_t)(s * STG_HALFS) * 2;
        const uint32_t sB = sA + A_HALFS * 2;
#pragma unroll
        for (int kk = 0; kk < BK / 16; kk++) {
            const int kb = kk * 16;
            uint32_t af[4][4], bf[NFN][2];
#pragma unroll
            for (int fm = 0; fm < 4; fm++)
                ldsm_x4(af[fm][0], af[fm][1], af[fm][2], af[fm][3],
                        sA + (uint32_t)((a_row + fm * 16) * STRH + kb + a_colh) * 2);
#pragma unroll
            for (int p = 0; p < NPAIR; p++)
                ldsm_x4(bf[2 * p][0], bf[2 * p][1], bf[2 * p + 1][0], bf[2 * p + 1][1],
                        sB + (uint32_t)((wn * WN + p * 16 + b_row) * STRH + kb + b_colh) * 2);
#pragma unroll
            for (int fm = 0; fm < 4; fm++)
#pragma unroll
                for (int fn = 0; fn < NFN; fn++)
                    mma_f16(acc[fm][fn], af[fm], bf[fn]);
        }
        __syncthreads();
        s = (s + 1) % 3;
    }

#pragma unroll
    for (int fm = 0; fm < 4; fm++) {
        int r = row0 + wm * 64 + fm * 16 + gid;
#pragma unroll
        for (int fn = 0; fn < NFN; fn++) {
            int cbase = col0 + wn * WN + fn * 8 + t4 * 2;
            float2* p0 = (float2*)&C[(size_t)r * N + cbase];
            float2* p1 = (float2*)&C[(size_t)(r + 8) * N + cbase];
            *p0 = make_float2(acc[fm][fn][0], acc[fm][fn][1]);
            *p1 = make_float2(acc[fm][fn][2], acc[fm][fn][3]);
        }
    }
}

// ---------------------------------------------------------------------------
// Fused fp32->fp16 conversion of x, W_in, W_out (one launch)
// ---------------------------------------------------------------------------
#define N4_X  (TOKENS * DMODEL / 4)
#define N4_WI (2 * DINNER * DMODEL / 4)
#define N4_WO (DMODEL * DINNER / 4)

__global__ void cvt_all_k(const float* __restrict__ x, const float* __restrict__ Wi,
                          const float* __restrict__ Wo) {
    int i = blockIdx.x * blockDim.x + threadIdx.x;
    const float* src; __half* dst; int off;
    if (i < N4_X)                  { src = x;  dst = g_xh;  off = i; }
    else if (i < N4_X + N4_WI)     { src = Wi; dst = g_wh;  off = i - N4_X; }
    else if (i < N4_X + N4_WI + N4_WO) { src = Wo; dst = g_woh; off = i - N4_X - N4_WI; }
    else return;
    float4 v = ((const float4*)src)[off];
    __half2 h0 = __float22half2_rn(make_float2(v.x, v.y));
    __half2 h1 = __float22half2_rn(make_float2(v.z, v.w));
    ((uint2*)dst)[off] = make_uint2(*(uint32_t*)&h0, *(uint32_t*)&h1);
}

// ---------------------------------------------------------------------------
// Causal depthwise conv (width 4) + bias + SiLU on first half of xz -> g_xi
// ---------------------------------------------------------------------------
__global__ void conv_silu_k(const float* __restrict__ cw, const float* __restrict__ cb) {
    int idx = blockIdx.x * blockDim.x + threadIdx.x;
    int d = idx & (DINNER - 1);
    int t = idx >> 11;
    int l = t & (SEQL - 1);
    float w0 = cw[d * 4 + 0], w1 = cw[d * 4 + 1], w2 = cw[d * 4 + 2], w3 = cw[d * 4 + 3];
    float acc = cb[d];
    size_t base = (size_t)t * (2 * DINNER) + d;
    if (l >= 3) acc += g_xz[base - 3 * (size_t)(2 * DINNER)] * w0;
    if (l >= 2) acc += g_xz[base - 2 * (size_t)(2 * DINNER)] * w1;
    if (l >= 1) acc += g_xz[base - 1 * (size_t)(2 * DINNER)] * w2;
    acc += g_xz[base] * w3;
    g_xi[idx] = acc / (1.f + __expf(-acc));
}

// ---------------------------------------------------------------------------
// x_dbl split-K partials. k-major smem stage: compute reads are 2x LDS.128
// (broadcast across the 33 e-threads of a ty-group) + 1 LDS.32 per 8 FMA.
// Same values, same k-order as before -> bit-identical.
// ---------------------------------------------------------------------------
__global__ void xdbl_part_k(const float* __restrict__ Wx) {
    __shared__ float Xs[32][72];      // [k][token], 64 tokens + pad (16B-aligned rows)
    __shared__ float Ws[33][33];
    const int tx = threadIdx.x, ty = threadIdx.y;   // (33,8)
    const int tid = ty * 33 + tx;
    const int tok0 = blockIdx.x * 64;
    const int kbase = blockIdx.y * 256;
    float acc[8] = {};
    for (int k0 = kbase; k0 < kbase + 256; k0 += 32) {
        for (int i = tid; i < 64 * 32; i += 264) {
            int tt = i >> 5, kk = i & 31;
            Xs[kk][tt] = g_xi[(size_t)(tok0 + tt) * DINNER + k0 + kk];
        }
        for (int i = tid; i < 33 * 32; i += 264) {
            int e = i >> 5, kk = i & 31;
            Ws[e][kk] = Wx[(size_t)e * DINNER + k0 + kk];
        }
        __syncthreads();
#pragma unroll
        for (int kk = 0; kk < 32; kk++) {
            float w = Ws[tx][kk];
            const float4* xr = (const float4*)&Xs[kk][ty * 8];
            float4 x0 = xr[0], x1 = xr[1];
            acc[0] += x0.x * w; acc[1] += x0.y * w;
            acc[2] += x0.z * w; acc[3] += x0.w * w;
            acc[4] += x1.x * w; acc[5] += x1.y * w;
            acc[6] += x1.z * w; acc[7] += x1.w * w;
        }
        __syncthreads();
    }
#pragma unroll
    for (int i = 0; i < 8; i++)
        g_dbcp[blockIdx.y][(size_t)(tok0 + ty * 8 + i) * 33 + tx] = acc[i];
}

__global__ void xdbl_reduce_k() {
    int i = blockIdx.x * blockDim.x + threadIdx.x;
    if (i >= TOKENS * 33) return;
    float s = 0.f;
#pragma unroll
    for (int p = 0; p < 8; p++) s += g_dbcp[p][i];
    g_dbc[i] = s;
}

// ---------------------------------------------------------------------------
// Selective scan with cross-chunk register prefetch: chunk c+1's gmem loads
// issue before chunk c's compute, hiding LDG latency (was exposed 64x/block).
// Arithmetic unchanged -> bit-identical.
// ---------------------------------------------------------------------------
#define CH 32
#define CPB 8
#define PSTRIDE 17
#define NCHUNK (SEQL / CH)

__global__ void __launch_bounds__(128, 4)
scan_k(const float* __restrict__ A_log, const float* __restrict__ Dvec,
       const float* __restrict__ Wdt, const float* __restrict__ bdt) {
    __shared__ float sB[CH][16], sC[CH][16];
    __shared__ float sX[CH][CPB], sZ[CH][CPB], sDT[CH][CPB];
    __shared__ float sP[CH][CPB * PSTRIDE];
    const int tid = threadIdx.x;              // 128
    const int dd = tid >> 4, n = tid & 15;    // channel 0..7, state 0..15
    const int q8 = tid & 7;                   // channel index for IO phases
    const int b = blockIdx.y;
    const int d0 = blockIdx.x * CPB;

    const float a  = -__expf(A_log[(d0 + dd) * DSTATE + n]);
    const float wq = Wdt[d0 + q8];
    const float bq = bdt[d0 + q8];
    const float Dq = Dvec[d0 + q8];
    float h = 0.f;

    float rdbc[9], rx[2], rz[2], rdt[2];

    auto prefetch = [&](int c) {
        const int tok0 = b * SEQL + c * CH;
#pragma unroll
        for (int j = 0; j < 9; j++) {
            int i = tid + j * 128;
            if (i < CH * 33) {
                int tt = i / 33, e = i - tt * 33;
                rdbc[j] = g_dbc[(size_t)(tok0 + tt) * 33 + e];
            }
        }
#pragma unroll
        for (int j = 0; j < 2; j++) {
            int tt = (tid + j * 128) >> 3;
            rx[j]  = g_xi[(size_t)(tok0 + tt) * DINNER + d0 + q8];
            rz[j]  = g_xz[(size_t)(tok0 + tt) * (2 * DINNER) + DINNER + d0 + q8];
            rdt[j] = g_dbc[(size_t)(tok0 + tt) * 33];
        }
    };
    auto commit = [&]() {
#pragma unroll
        for (int j = 0; j < 9; j++) {
            int i = tid + j * 128;
            if (i < CH * 33) {
                int tt = i / 33, e = i - tt * 33;
                float v = rdbc[j];
                if (e >= 17)     sC[tt][e - 17] = v;
                else if (e >= 1) sB[tt][e - 1]  = v;
            }
        }
#pragma unroll
        for (int j = 0; j < 2; j++) {
            int tt = (tid + j * 128) >> 3;
            sX[tt][q8] = rx[j];
            sZ[tt][q8] = rz[j];
            float u = rdt[j] * wq + bq;
            sDT[tt][q8] = (u > 20.f) ? u : log1pf(__expf(u));
        }
    };

    prefetch(0);
    for (int c = 0; c < NCHUNK; c++) {
        const int tok0 = b * SEQL + c * CH;
        commit();
        __syncthreads();
        if (c + 1 < NCHUNK) prefetch(c + 1);   // LDGs overlap loops + output

        // Loop A: independent per-step precompute
        float dA[CH], bx[CH];
#pragma unroll
        for (int t = 0; t < CH; t++) {
            float dtv = sDT[t][dd];
            dA[t] = __expf(dtv * a);
            bx[t] = (dtv * sB[t][n]) * sX[t][dd];
        }
        // Loop B: pure FFMA recurrence; C-multiply + STS off-chain
#pragma unroll
        for (int t = 0; t < CH; t++) {
            h = fmaf(dA[t], h, bx[t]);
            sP[t][dd * PSTRIDE + n] = h * sC[t][n];
        }
        __syncthreads();

        for (int i = tid; i < CH * CPB; i += 128) {
            int tt = i >> 3;
            float s = 0.f;
#pragma unroll
            for (int j = 0; j < 16; j++) s += sP[tt][q8 * PSTRIDE + j];
            float xv = sX[tt][q8], zv = sZ[tt][q8];
            float yv = (s + Dq * xv) * (zv / (1.f + __expf(-zv)));
            g_yh[(size_t)(tok0 + tt) * DINNER + d0 + q8] = __float2half_rn(yv);
        }
        __syncthreads();
    }
}

// ---------------------------------------------------------------------------
extern "C" void kernel_launch(void* const* d_in, const int* in_sizes, int n_in,
                              void* d_out, int out_size) {
    const float* x     = (const float*)d_in[0];
    const float* W_in  = (const float*)d_in[1];
    const float* convw = (const float*)d_in[2];
    const float* convb = (const float*)d_in[3];
    const float* W_x   = (const float*)d_in[4];
    const float* W_dt  = (const float*)d_in[5];
    const float* b_dt  = (const float*)d_in[6];
    const float* A_log = (const float*)d_in[7];
    const float* Dv    = (const float*)d_in[8];
    const float* W_out = (const float*)d_in[9];
    float* out = (float*)d_out;

    float *xz;
    __half *xh, *wh, *woh, *yh;
    cudaGetSymbolAddress((void**)&xz,  g_xz);
    cudaGetSymbolAddress((void**)&xh,  g_xh);
    cudaGetSymbolAddress((void**)&wh,  g_wh);
    cudaGetSymbolAddress((void**)&woh, g_woh);
    cudaGetSymbolAddress((void**)&yh,  g_yh);

    cudaFuncSetAttribute(h_gemm_nt, cudaFuncAttributeMaxDynamicSharedMemorySize, GEMM_SMEM);

    // 0) convert all GEMM operands to fp16 (single launch)
    const int n4tot = N4_X + N4_WI + N4_WO;
    cvt_all_k<<<(n4tot + 255) / 256, 256>>>(x, W_in, W_out);

    // 1) xz = x @ W_in^T   [4096 x 4096], K=1024
    h_gemm_nt<<<dim3(4096 / BN, TOKENS / BM), 256, GEMM_SMEM>>>(xh, wh, xz, TOKENS, 4096, DMODEL);

    // 2) causal depthwise conv + silu -> g_xi
    conv_silu_k<<<(TOKENS * DINNER) / 256, 256>>>(convw, convb);

    // 3) x_dbl = xi @ W_x^T (split-K + deterministic reduce)
    xdbl_part_k<<<dim3(TOKENS / 64, 8), dim3(33, 8)>>>(W_x);
    xdbl_reduce_k<<<(TOKENS * 33 + 255) / 256, 256>>>();

    // 4) selective scan -> g_yh (half)
    scan_k<<<dim3(DINNER / CPB, 2), 128>>>(A_log, Dv, W_dt, b_dt);

    // 5) out = y @ W_out^T   [4096 x 1024], K=2048
    h_gemm_nt<<<dim3(DMODEL / BN, TOKENS / BM), 256, GEMM_SMEM>>>(yh, woh, out, TOKENS, DMODEL, DINNER);
}